// round 1
// baseline (speedup 1.0000x reference)
#include <cuda_runtime.h>
#include <cstdint>

// ---------------------------------------------------------------------------
// Problem constants (fixed by the reference): B=1, N1=512, N2=2048, C=1024,
// H=8, hd=128, SCALE=25, SIM_THRESH=0.75, CONF_SIM_THRESH=0.99
// ---------------------------------------------------------------------------

// ----------------------------- scratch layout ------------------------------
constexpr size_t OFF_QCLS  = 0;                                  // [512,1024]
constexpr size_t OFF_QREG  = OFF_QCLS  + (size_t)512 * 1024;     // [512,1024]
constexpr size_t OFF_KVCLS = OFF_QREG  + (size_t)512 * 1024;     // [2048,2048] (k | v)
constexpr size_t OFF_KVREG = OFF_KVCLS + (size_t)2048 * 2048;    // [2048,2048]
constexpr size_t OFF_VNCLS = OFF_KVREG + (size_t)2048 * 2048;    // [2048,1024]
constexpr size_t OFF_VNREG = OFF_VNCLS + (size_t)2048 * 1024;    // [2048,1024]
constexpr size_t OFF_SCCLS = OFF_VNREG + (size_t)2048 * 1024;    // [8,512,2048]
constexpr size_t OFF_SCREG = OFF_SCCLS + (size_t)8 * 512 * 2048; // [8,512,2048]
constexpr size_t OFF_ATTN  = OFF_SCREG + (size_t)8 * 512 * 2048; // [8,512,2048]
constexpr size_t OFF_ASUM  = OFF_ATTN  + (size_t)8 * 512 * 2048; // [512,2048]
constexpr size_t OFF_SIMC  = OFF_ASUM  + (size_t)512 * 2048;     // [512,2048]
constexpr size_t OFF_SIMR  = OFF_SIMC  + (size_t)512 * 2048;     // [512,2048]
constexpr size_t OFF_XCC   = OFF_SIMR  + (size_t)512 * 2048;     // [512,2048] concat(x, x_ori) cls
constexpr size_t OFF_XCR   = OFF_XCC   + (size_t)512 * 2048;     // [512,2048] reg
constexpr size_t OFF_S2    = OFF_XCR   + (size_t)512 * 2048;     // [512,2048] sim_round2
constexpr size_t OFF_OW    = OFF_S2    + (size_t)512 * 2048;     // [512,2048] obj_w
constexpr size_t SCRATCH_TOTAL = OFF_OW + (size_t)512 * 2048;

__device__ float g_scratch[SCRATCH_TOTAL];

// ------------------------------- GEMM (NN) ---------------------------------
// C[m,n] = sum_k A[m,k]*B[k,n] (+bias[n]). 128x128x16 tiles, 256 thr, 8x8/thr.
// All of M, N must be multiples of 128; K multiple of 16; lda/ldb/ldc mult. 4.
#define BM 128
#define BN 128
#define BKD 16

template <bool BIAS>
__global__ void __launch_bounds__(256)
gemm_nn(const float* __restrict__ A, const float* __restrict__ B,
        const float* __restrict__ bias, float* __restrict__ C,
        int K, int lda, int ldb, int ldc,
        long long abstride, long long bbstride, long long cbstride)
{
    A += (long long)blockIdx.z * abstride;
    B += (long long)blockIdx.z * bbstride;
    C += (long long)blockIdx.z * cbstride;
    const int bm = blockIdx.y * BM;
    const int bn = blockIdx.x * BN;

    __shared__ float As[BKD][BM];
    __shared__ float Bs[BKD][BN];

    const int tid = threadIdx.x;
    const int tx = tid & 15;   // n-group
    const int ty = tid >> 4;   // m-group

    // A loader: row = tid>>2 (+64), k4 = (tid&3)*4  -> coalesced float4 along k
    const int ar = tid >> 2;
    const int ak = (tid & 3) << 2;
    // B loader: k = tid>>5 (+8), n4 = (tid&31)*4    -> coalesced float4 along n
    const int bk = tid >> 5;
    const int bn4 = (tid & 31) << 2;

    const float* Ap0 = A + (size_t)(bm + ar) * lda + ak;
    const float* Ap1 = A + (size_t)(bm + ar + 64) * lda + ak;
    const float* Bp0 = B + (size_t)bk * ldb + bn + bn4;
    const float* Bp1 = B + (size_t)(bk + 8) * ldb + bn + bn4;

    float acc[8][8];
#pragma unroll
    for (int i = 0; i < 8; i++)
#pragma unroll
        for (int j = 0; j < 8; j++) acc[i][j] = 0.f;

    for (int k0 = 0; k0 < K; k0 += BKD) {
        float4 a0 = *(const float4*)(Ap0 + k0);
        float4 a1 = *(const float4*)(Ap1 + k0);
        float4 b0 = *(const float4*)(Bp0 + (size_t)k0 * ldb);
        float4 b1 = *(const float4*)(Bp1 + (size_t)k0 * ldb);

        As[ak + 0][ar] = a0.x; As[ak + 1][ar] = a0.y;
        As[ak + 2][ar] = a0.z; As[ak + 3][ar] = a0.w;
        As[ak + 0][ar + 64] = a1.x; As[ak + 1][ar + 64] = a1.y;
        As[ak + 2][ar + 64] = a1.z; As[ak + 3][ar + 64] = a1.w;
        *(float4*)&Bs[bk][bn4] = b0;
        *(float4*)&Bs[bk + 8][bn4] = b1;
        __syncthreads();

#pragma unroll
        for (int kk = 0; kk < BKD; kk++) {
            float a[8], b[8];
            *(float4*)&a[0] = *(const float4*)&As[kk][ty * 8];
            *(float4*)&a[4] = *(const float4*)&As[kk][ty * 8 + 4];
            *(float4*)&b[0] = *(const float4*)&Bs[kk][tx * 8];
            *(float4*)&b[4] = *(const float4*)&Bs[kk][tx * 8 + 4];
#pragma unroll
            for (int i = 0; i < 8; i++)
#pragma unroll
                for (int j = 0; j < 8; j++) acc[i][j] += a[i] * b[j];
        }
        __syncthreads();
    }

    float4 bv0 = {0, 0, 0, 0}, bv1 = {0, 0, 0, 0};
    if (BIAS) {
        bv0 = *(const float4*)(bias + bn + tx * 8);
        bv1 = *(const float4*)(bias + bn + tx * 8 + 4);
    }
#pragma unroll
    for (int i = 0; i < 8; i++) {
        float* crow = C + (size_t)(bm + ty * 8 + i) * ldc + bn + tx * 8;
        float4 v0 = {acc[i][0], acc[i][1], acc[i][2], acc[i][3]};
        float4 v1 = {acc[i][4], acc[i][5], acc[i][6], acc[i][7]};
        if (BIAS) {
            v0.x += bv0.x; v0.y += bv0.y; v0.z += bv0.z; v0.w += bv0.w;
            v1.x += bv1.x; v1.y += bv1.y; v1.z += bv1.z; v1.w += bv1.w;
        }
        *(float4*)(crow) = v0;
        *(float4*)(crow + 4) = v1;
    }
}

// ------------------------------- GEMM (NT) ---------------------------------
// C[m,n] = sum_k A[m,k]*B[n,k]. Same tiling. M,N mult of 128, K mult of 16.
__global__ void __launch_bounds__(256)
gemm_nt(const float* __restrict__ A, const float* __restrict__ B,
        float* __restrict__ C,
        int K, int lda, int ldb, int ldc,
        long long abstride, long long bbstride, long long cbstride)
{
    A += (long long)blockIdx.z * abstride;
    B += (long long)blockIdx.z * bbstride;
    C += (long long)blockIdx.z * cbstride;
    const int bm = blockIdx.y * BM;
    const int bn = blockIdx.x * BN;

    __shared__ float As[BKD][BM];
    __shared__ float Bs[BKD][BN];

    const int tid = threadIdx.x;
    const int tx = tid & 15;
    const int ty = tid >> 4;

    const int ar = tid >> 2;
    const int ak = (tid & 3) << 2;
    // B loader (NT): n = tid&127, k4 = (tid>>7)*4 (and +8)
    const int bnr = tid & 127;
    const int bkq = (tid >> 7) << 2;  // 0 or 4

    const float* Ap0 = A + (size_t)(bm + ar) * lda + ak;
    const float* Ap1 = A + (size_t)(bm + ar + 64) * lda + ak;
    const float* Bp = B + (size_t)(bn + bnr) * ldb + bkq;

    float acc[8][8];
#pragma unroll
    for (int i = 0; i < 8; i++)
#pragma unroll
        for (int j = 0; j < 8; j++) acc[i][j] = 0.f;

    for (int k0 = 0; k0 < K; k0 += BKD) {
        float4 a0 = *(const float4*)(Ap0 + k0);
        float4 a1 = *(const float4*)(Ap1 + k0);
        float4 b0 = *(const float4*)(Bp + k0);
        float4 b1 = *(const float4*)(Bp + k0 + 8);

        As[ak + 0][ar] = a0.x; As[ak + 1][ar] = a0.y;
        As[ak + 2][ar] = a0.z; As[ak + 3][ar] = a0.w;
        As[ak + 0][ar + 64] = a1.x; As[ak + 1][ar + 64] = a1.y;
        As[ak + 2][ar + 64] = a1.z; As[ak + 3][ar + 64] = a1.w;
        Bs[bkq + 0][bnr] = b0.x; Bs[bkq + 1][bnr] = b0.y;
        Bs[bkq + 2][bnr] = b0.z; Bs[bkq + 3][bnr] = b0.w;
        Bs[bkq + 8][bnr] = b1.x; Bs[bkq + 9][bnr] = b1.y;
        Bs[bkq + 10][bnr] = b1.z; Bs[bkq + 11][bnr] = b1.w;
        __syncthreads();

#pragma unroll
        for (int kk = 0; kk < BKD; kk++) {
            float a[8], b[8];
            *(float4*)&a[0] = *(const float4*)&As[kk][ty * 8];
            *(float4*)&a[4] = *(const float4*)&As[kk][ty * 8 + 4];
            *(float4*)&b[0] = *(const float4*)&Bs[kk][tx * 8];
            *(float4*)&b[4] = *(const float4*)&Bs[kk][tx * 8 + 4];
#pragma unroll
            for (int i = 0; i < 8; i++)
#pragma unroll
                for (int j = 0; j < 8; j++) acc[i][j] += a[i] * b[j];
        }
        __syncthreads();
    }

#pragma unroll
    for (int i = 0; i < 8; i++) {
        float* crow = C + (size_t)(bm + ty * 8 + i) * ldc + bn + tx * 8;
        float4 v0 = {acc[i][0], acc[i][1], acc[i][2], acc[i][3]};
        float4 v1 = {acc[i][4], acc[i][5], acc[i][6], acc[i][7]};
        *(float4*)(crow) = v0;
        *(float4*)(crow + 4) = v1;
    }
}

// --------------------------- L2 normalize (per head) -----------------------
// One warp per (row, head) 128-vector. dst may equal src.
__global__ void __launch_bounds__(256)
l2norm_k(const float* __restrict__ src, float* __restrict__ dst,
         int lds, int ldd, int nvec)
{
    int vec = blockIdx.x * 8 + (threadIdx.x >> 5);
    int lane = threadIdx.x & 31;
    if (vec >= nvec) return;
    int row = vec >> 3, h = vec & 7;
    const float* s = src + (size_t)row * lds + h * 128 + lane * 4;
    float4 v = *(const float4*)s;
    float ss = v.x * v.x + v.y * v.y + v.z * v.z + v.w * v.w;
#pragma unroll
    for (int o = 16; o; o >>= 1) ss += __shfl_xor_sync(0xffffffffu, ss, o);
    float inv = 1.0f / sqrtf(ss);
    float4 o4 = {v.x * inv, v.y * inv, v.z * inv, v.w * inv};
    *(float4*)(dst + (size_t)row * ldd + h * 128 + lane * 4) = o4;
}

// ------------------------------ block reductions ---------------------------
static __device__ __forceinline__ float blockReduceMax(float v) {
    __shared__ float s[8];
#pragma unroll
    for (int o = 16; o; o >>= 1) v = fmaxf(v, __shfl_xor_sync(0xffffffffu, v, o));
    if ((threadIdx.x & 31) == 0) s[threadIdx.x >> 5] = v;
    __syncthreads();
    v = s[threadIdx.x & 7];
#pragma unroll
    for (int o = 4; o; o >>= 1) v = fmaxf(v, __shfl_xor_sync(0xffffffffu, v, o));
    __syncthreads();
    return v;
}
static __device__ __forceinline__ float blockReduceSum(float v) {
    __shared__ float s[8];
#pragma unroll
    for (int o = 16; o; o >>= 1) v += __shfl_xor_sync(0xffffffffu, v, o);
    if ((threadIdx.x & 31) == 0) s[threadIdx.x >> 5] = v;
    __syncthreads();
    v = s[threadIdx.x & 7];
#pragma unroll
    for (int o = 4; o; o >>= 1) v += __shfl_xor_sync(0xffffffffu, v, o);
    __syncthreads();
    return v;
}

// --------------------- softmax blend over both branches --------------------
// One block per query q (512 blocks, 256 threads). Loops over 8 heads.
// attn[h,q,k] = 0.5*softmax(25*cs[k]*sc_cls)[k] + 0.5*softmax(25*sc_reg)[k]
// asum[q,k]   = sum_h attn[h,q,k]
__global__ void __launch_bounds__(256)
softmax_combine(const float* __restrict__ sc_cls, const float* __restrict__ sc_reg,
                const float* __restrict__ cls_score,
                float* __restrict__ attn, float* __restrict__ asum)
{
    const int q = blockIdx.x;
    const int tid = threadIdx.x;
    float cs[8], accum[8];
#pragma unroll
    for (int j = 0; j < 8; j++) {
        cs[j] = cls_score[j * 256 + tid];
        accum[j] = 0.f;
    }
    for (int h = 0; h < 8; h++) {
        const float* pc = sc_cls + ((size_t)h * 512 + q) * 2048;
        const float* pr = sc_reg + ((size_t)h * 512 + q) * 2048;
        float c[8], r[8];
        float mc = -1e30f, mr = -1e30f;
#pragma unroll
        for (int j = 0; j < 8; j++) {
            int k = j * 256 + tid;
            c[j] = pc[k] * 25.0f * cs[j];
            r[j] = pr[k] * 25.0f;
            mc = fmaxf(mc, c[j]);
            mr = fmaxf(mr, r[j]);
        }
        mc = blockReduceMax(mc);
        mr = blockReduceMax(mr);
        float sc = 0.f, sr = 0.f;
#pragma unroll
        for (int j = 0; j < 8; j++) {
            c[j] = expf(c[j] - mc);
            r[j] = expf(r[j] - mr);
            sc += c[j];
            sr += r[j];
        }
        sc = blockReduceSum(sc);
        sr = blockReduceSum(sr);
        float ic = 0.5f / sc, ir = 0.5f / sr;
        float* pa = attn + ((size_t)h * 512 + q) * 2048;
#pragma unroll
        for (int j = 0; j < 8; j++) {
            float a = c[j] * ic + r[j] * ir;
            pa[j * 256 + tid] = a;
            accum[j] += a;
        }
    }
#pragma unroll
    for (int j = 0; j < 8; j++) asum[(size_t)q * 2048 + j * 256 + tid] = accum[j];
}

// ------------------ masked renormalized second-round weights ---------------
// One block per q. p = softmax(asum/8); s2 = renorm(simC/8>0.75 ? p : 0);
// ow = renorm(simR/8>0.99 ? s2 : 0)
__global__ void __launch_bounds__(256)
mask_renorm(const float* __restrict__ asum, const float* __restrict__ simc,
            const float* __restrict__ simr,
            float* __restrict__ s2, float* __restrict__ ow)
{
    const int q = blockIdx.x;
    const int tid = threadIdx.x;
    float a[8];
    float mx = -1e30f;
#pragma unroll
    for (int j = 0; j < 8; j++) {
        a[j] = asum[(size_t)q * 2048 + j * 256 + tid] * 0.125f;
        mx = fmaxf(mx, a[j]);
    }
    mx = blockReduceMax(mx);
    float sum = 0.f;
#pragma unroll
    for (int j = 0; j < 8; j++) {
        a[j] = expf(a[j] - mx);
        sum += a[j];
    }
    sum = blockReduceSum(sum);
    float inv = 1.0f / sum;
    float sm = 0.f;
#pragma unroll
    for (int j = 0; j < 8; j++) {
        int k = j * 256 + tid;
        float m = (simc[(size_t)q * 2048 + k] * 0.125f > 0.75f) ? 1.0f : 0.0f;
        a[j] = a[j] * inv * m;
        sm += a[j];
    }
    sm = blockReduceSum(sm);
    inv = 1.0f / sm;
    float so = 0.f;
    float o[8];
#pragma unroll
    for (int j = 0; j < 8; j++) {
        int k = j * 256 + tid;
        a[j] *= inv;
        s2[(size_t)q * 2048 + k] = a[j];
        float m = (simr[(size_t)q * 2048 + k] * 0.125f > 0.99f) ? 1.0f : 0.0f;
        o[j] = a[j] * m;
        so += o[j];
    }
    so = blockReduceSum(so);
    inv = 1.0f / so;
#pragma unroll
    for (int j = 0; j < 8; j++) ow[(size_t)q * 2048 + j * 256 + tid] = o[j] * inv;
}

// -------------------------- copy x_ori into concat -------------------------
// xcat[q, 1024 + c] = kv[q, 1024 + c] for q<512 (v part of first 512 rows)
__global__ void __launch_bounds__(256)
copy_xori(const float* __restrict__ kv, float* __restrict__ xcat)
{
    int idx = blockIdx.x * 256 + threadIdx.x;  // 512*256 float4s
    int q = idx >> 8;
    int c4 = idx & 255;
    size_t off = (size_t)q * 2048 + 1024 + (size_t)c4 * 4;
    *(float4*)(xcat + off) = *(const float4*)(kv + off);
}

// --------------------------------- launch ----------------------------------
extern "C" void kernel_launch(void* const* d_in, const int* in_sizes, int n_in,
                              void* d_out, int out_size)
{
    const float* x_cls     = (const float*)d_in[0];
    const float* x_reg     = (const float*)d_in[1];
    const float* cls_score = (const float*)d_in[2];
    // d_in[3] fg_score: unused by the reference math
    const float* W_q_cls   = (const float*)d_in[4];
    const float* W_kv_cls  = (const float*)d_in[5];
    const float* W_q_reg   = (const float*)d_in[6];
    const float* W_kv_reg  = (const float*)d_in[7];
    const float* W_lin     = (const float*)d_in[8];
    const float* b_lin     = (const float*)d_in[9];
    const float* W_lin_reg = (const float*)d_in[10];
    const float* b_lin_reg = (const float*)d_in[11];
    float* out = (float*)d_out;

    float* S = nullptr;
    cudaGetSymbolAddress((void**)&S, g_scratch);
    float* qc   = S + OFF_QCLS;
    float* qr   = S + OFF_QREG;
    float* kvc  = S + OFF_KVCLS;
    float* kvr  = S + OFF_KVREG;
    float* vnc  = S + OFF_VNCLS;
    float* vnr  = S + OFF_VNREG;
    float* scc  = S + OFF_SCCLS;
    float* scr  = S + OFF_SCREG;
    float* attn = S + OFF_ATTN;
    float* asum = S + OFF_ASUM;
    float* simc = S + OFF_SIMC;
    float* simr = S + OFF_SIMR;
    float* xcc  = S + OFF_XCC;
    float* xcr  = S + OFF_XCR;
    float* s2   = S + OFF_S2;
    float* ow   = S + OFF_OW;

    const long long HSTR = 512LL * 2048LL;  // per-head score/attn stride
    float* out_reg = out + (size_t)512 * 3072;

    // 1) Projections
    gemm_nn<false><<<dim3(8, 4, 1), 256>>>(x_cls, W_q_cls, nullptr, qc,
                                           1024, 1024, 1024, 1024, 0, 0, 0);
    gemm_nn<false><<<dim3(16, 16, 1), 256>>>(x_cls, W_kv_cls, nullptr, kvc,
                                             1024, 1024, 2048, 2048, 0, 0, 0);
    gemm_nn<false><<<dim3(8, 4, 1), 256>>>(x_reg, W_q_reg, nullptr, qr,
                                           1024, 1024, 1024, 1024, 0, 0, 0);
    gemm_nn<false><<<dim3(16, 16, 1), 256>>>(x_reg, W_kv_reg, nullptr, kvr,
                                             1024, 1024, 2048, 2048, 0, 0, 0);

    // 2) L2 normalization (q,k in-place; v -> v_n)
    l2norm_k<<<512, 256>>>(qc, qc, 1024, 1024, 512 * 8);
    l2norm_k<<<512, 256>>>(qr, qr, 1024, 1024, 512 * 8);
    l2norm_k<<<2048, 256>>>(kvc, kvc, 2048, 2048, 2048 * 8);
    l2norm_k<<<2048, 256>>>(kvr, kvr, 2048, 2048, 2048 * 8);
    l2norm_k<<<2048, 256>>>(kvc + 1024, vnc, 2048, 1024, 2048 * 8);
    l2norm_k<<<2048, 256>>>(kvr + 1024, vnr, 2048, 1024, 2048 * 8);

    // 3) Attention scores per head (q_n @ k_n^T), batched over 8 heads
    gemm_nt<<<dim3(16, 4, 8), 256>>>(qc, kvc, scc, 128, 1024, 2048, 2048,
                                     128, 128, HSTR);
    gemm_nt<<<dim3(16, 4, 8), 256>>>(qr, kvr, scr, 128, 1024, 2048, 2048,
                                     128, 128, HSTR);

    // 4) Head-summed v-similarities collapse to one full-width NT GEMM each
    gemm_nt<<<dim3(16, 4, 1), 256>>>(vnc, vnc, simc, 1024, 1024, 1024, 2048,
                                     0, 0, 0);
    gemm_nt<<<dim3(16, 4, 1), 256>>>(vnr, vnr, simr, 1024, 1024, 1024, 2048,
                                     0, 0, 0);

    // 5) Blend softmaxes, produce attn[8,512,2048] and head-sum
    softmax_combine<<<512, 256>>>(scc, scr, cls_score, attn, asum);

    // 6) x = attn @ v (per head), written into concat cols [0,1024)
    gemm_nn<false><<<dim3(1, 4, 8), 256>>>(attn, kvc + 1024, nullptr, xcc,
                                           2048, 2048, 2048, 2048,
                                           HSTR, 128, 128);
    gemm_nn<false><<<dim3(1, 4, 8), 256>>>(attn, kvr + 1024, nullptr, xcr,
                                           2048, 2048, 2048, 2048,
                                           HSTR, 128, 128);

    // 7) x_ori into concat cols [1024,2048)
    copy_xori<<<512, 256>>>(kvc, xcc);
    copy_xori<<<512, 256>>>(kvr, xcr);

    // 8) second-round masked weights
    mask_renorm<<<512, 256>>>(asum, simc, simr, s2, ow);

    // 9) Output linears -> out columns [1024, 3072)
    gemm_nn<true><<<dim3(16, 4, 1), 256>>>(xcc, W_lin, b_lin, out + 1024,
                                           2048, 2048, 2048, 3072, 0, 0, 0);
    gemm_nn<true><<<dim3(16, 4, 1), 256>>>(xcr, W_lin_reg, b_lin_reg,
                                           out_reg + 1024,
                                           2048, 2048, 2048, 3072, 0, 0, 0);

    // 10) Averaged support features -> out columns [0, 1024)
    gemm_nn<false><<<dim3(8, 4, 1), 256>>>(s2, kvc + 1024, nullptr, out,
                                           2048, 2048, 2048, 3072, 0, 0, 0);
    gemm_nn<false><<<dim3(8, 4, 1), 256>>>(ow, kvr + 1024, nullptr, out_reg,
                                           2048, 2048, 2048, 3072, 0, 0, 0);
}

// round 3
// speedup vs baseline: 2.9623x; 2.9623x over previous
#include <cuda_runtime.h>
#include <cuda_fp16.h>
#include <cstdint>

// ===========================================================================
// Fixed shapes: B=1, N1=512, N2=2048, C=1024, H=8, hd=128
// All GEMMs: warp-level mma.sync m16n8k16 fp16 with 3-term hi/lo split
// (error ~2^-21). Operands pre-split to fp16 hi/lo planes exactly once,
// fused into the surrounding elementwise kernels.
// ===========================================================================

constexpr size_t Mi = 1024 * 1024;

// ------------------------- fp32 scratch layout ------------------------------
constexpr size_t F_QC   = 0;                 // [512,1024]
constexpr size_t F_QR   = F_QC   + Mi / 2;
constexpr size_t F_KVC  = F_QR   + Mi / 2;   // [2048,2048]
constexpr size_t F_KVR  = F_KVC  + 4 * Mi;
constexpr size_t F_SCC  = F_KVR  + 4 * Mi;   // [8,512,2048]
constexpr size_t F_SCR  = F_SCC  + 8 * Mi;
constexpr size_t F_ASUM = F_SCR  + 8 * Mi;   // [512,2048]
constexpr size_t F_SIMC = F_ASUM + Mi;
constexpr size_t F_SIMR = F_SIMC + Mi;
constexpr size_t F_TOTAL = F_SIMR + Mi;
__device__ float g_scratch[F_TOTAL];

// ------------------------- fp16 plane layout -------------------------------
constexpr size_t HXCH  = 0;                  // x_cls  [2048,1024]
constexpr size_t HXCL  = HXCH  + 2 * Mi;
constexpr size_t HXRH  = HXCL  + 2 * Mi;
constexpr size_t HXRL  = HXRH  + 2 * Mi;
constexpr size_t HWQCH = HXRL  + 2 * Mi;     // W_q_cls^T [1024,1024]
constexpr size_t HWQCL = HWQCH + 1 * Mi;
constexpr size_t HWQRH = HWQCL + 1 * Mi;
constexpr size_t HWQRL = HWQRH + 1 * Mi;
constexpr size_t HWKCH = HWQRL + 1 * Mi;     // W_kv_cls^T [2048,1024]
constexpr size_t HWKCL = HWKCH + 2 * Mi;
constexpr size_t HWKRH = HWKCL + 2 * Mi;
constexpr size_t HWKRL = HWKRH + 2 * Mi;
constexpr size_t HWLCH = HWKRL + 2 * Mi;     // W_lin^T [2048,2048]
constexpr size_t HWLCL = HWLCH + 4 * Mi;
constexpr size_t HWLRH = HWLCL + 4 * Mi;
constexpr size_t HWLRL = HWLRH + 4 * Mi;
constexpr size_t HQCH  = HWLRL + 4 * Mi;     // q_cls norm [512,1024]
constexpr size_t HQCL  = HQCH  + Mi / 2;
constexpr size_t HQRH  = HQCL  + Mi / 2;
constexpr size_t HQRL  = HQRH  + Mi / 2;
constexpr size_t HKCH  = HQRL  + Mi / 2;     // k_cls norm [2048,1024]
constexpr size_t HKCL  = HKCH  + 2 * Mi;
constexpr size_t HKRH  = HKCL  + 2 * Mi;
constexpr size_t HKRL  = HKRH  + 2 * Mi;
constexpr size_t HVNCH = HKRL  + 2 * Mi;     // v_cls norm [2048,1024]
constexpr size_t HVNCL = HVNCH + 2 * Mi;
constexpr size_t HVNRH = HVNCL + 2 * Mi;
constexpr size_t HVNRL = HVNRH + 2 * Mi;
constexpr size_t HVTCH = HVNRL + 2 * Mi;     // v_cls^T [1024,2048]
constexpr size_t HVTCL = HVTCH + 2 * Mi;
constexpr size_t HVTRH = HVTCL + 2 * Mi;
constexpr size_t HVTRL = HVTRH + 2 * Mi;
constexpr size_t HATH  = HVTRL + 2 * Mi;     // attn [8,512,2048]
constexpr size_t HATL  = HATH  + 8 * Mi;
constexpr size_t HS2H  = HATL  + 8 * Mi;     // sim_round2 [512,2048]
constexpr size_t HS2L  = HS2H  + Mi;
constexpr size_t HOWH  = HS2L  + Mi;
constexpr size_t HOWL  = HOWH  + Mi;
constexpr size_t HXCCH = HOWL  + Mi;         // concat(x,x_ori) cls [512,2048]
constexpr size_t HXCCL = HXCCH + Mi;
constexpr size_t HXCRH = HXCCL + Mi;
constexpr size_t HXCRL = HXCRH + Mi;
constexpr size_t H_TOTAL = HXCRL + Mi;
__device__ __half g_half[H_TOTAL];

// ----------------------------- helpers -------------------------------------
__device__ __forceinline__ uint32_t smem_u32(const void* p) {
    uint32_t a;
    asm("{ .reg .u64 t; cvta.to.shared.u64 t, %1; cvt.u32.u64 %0, t; }"
        : "=r"(a) : "l"(p));
    return a;
}
__device__ __forceinline__ uint32_t pack2(__half a, __half b) {
    __half2 h = __halves2half2(a, b);
    return *(uint32_t*)&h;
}
__device__ __forceinline__ void split1(float x, __half& h, __half& l) {
    h = __float2half_rn(x);
    l = __float2half_rn(x - __half2float(h));
}
__device__ __forceinline__ void split4(float4 v, uint2& hi, uint2& lo) {
    __half h0, h1, h2, h3, l0, l1, l2, l3;
    split1(v.x, h0, l0); split1(v.y, h1, l1);
    split1(v.z, h2, l2); split1(v.w, h3, l3);
    hi.x = pack2(h0, h1); hi.y = pack2(h2, h3);
    lo.x = pack2(l0, l1); lo.y = pack2(l2, l3);
}
__device__ __forceinline__ void ldsm4(uint32_t* r, uint32_t addr) {
    asm volatile("ldmatrix.sync.aligned.m8n8.x4.shared.b16 {%0,%1,%2,%3}, [%4];"
                 : "=r"(r[0]), "=r"(r[1]), "=r"(r[2]), "=r"(r[3]) : "r"(addr));
}
__device__ __forceinline__ void mma16816(float* d, const uint32_t* a, const uint32_t* b) {
    asm volatile("mma.sync.aligned.m16n8k16.row.col.f32.f16.f16.f32 "
                 "{%0,%1,%2,%3}, {%4,%5,%6,%7}, {%8,%9}, {%0,%1,%2,%3};"
                 : "+f"(d[0]), "+f"(d[1]), "+f"(d[2]), "+f"(d[3])
                 : "r"(a[0]), "r"(a[1]), "r"(a[2]), "r"(a[3]),
                   "r"(b[0]), "r"(b[1]));
}

// ------------------------------- hgemm (NT) ---------------------------------
// C[M,N] = (Ah+Al)[M,K] * (Bh+Bl)[N,K]^T, 3-term split, fp32 accum.
// CTA 128x128x32, 8 warps (64x32 per warp), double-buffered smem.
// smem per stage: 4 planes * 128 rows * 80B = 40960 B; 2 stages = 81920 B.
constexpr int HG_SMEM = 81920;

template <bool BIAS, bool FOUT, bool SPLITOUT>
__global__ void __launch_bounds__(256)
hgemm(const __half* __restrict__ Ah_g, const __half* __restrict__ Al_g,
      const __half* __restrict__ Bh_g, const __half* __restrict__ Bl_g,
      const float* __restrict__ bias,
      float* C, __half* Chi, __half* Clo,
      int K, int lda, int ldb, int ldc,
      long long asb, long long bsb, long long csb)
{
    extern __shared__ char dsm[];
    const uint32_t sb = smem_u32(dsm);
    const int tid = threadIdx.x;

    Ah_g += (long long)blockIdx.z * asb + (long long)blockIdx.y * 128 * lda;
    Al_g += (long long)blockIdx.z * asb + (long long)blockIdx.y * 128 * lda;
    Bh_g += (long long)blockIdx.z * bsb + (long long)blockIdx.x * 128 * ldb;
    Bl_g += (long long)blockIdx.z * bsb + (long long)blockIdx.x * 128 * ldb;
    if (FOUT) C += (long long)blockIdx.z * csb;
    if (SPLITOUT) { Chi += (long long)blockIdx.z * csb; Clo += (long long)blockIdx.z * csb; }

    // loader: 512 uint4-chunks per plane (128 rows x 4 chunks of 16B)
    const int lrow = tid >> 2;        // 0..63 (+64 on second pass)
    const int lc16 = tid & 3;         // 16B chunk in 64B row

    const int lane = tid & 31, w = tid >> 5;
    const int wm = (w >> 2) << 6;     // warp m offset (0 or 64)
    const int wn = (w & 3) << 5;      // warp n offset (0..96)
    const int g = lane >> 3, r = lane & 7;
    const int a_r  = r + ((g & 1) << 3);
    const int a_kb = (g >> 1) << 3;
    const int b_r  = r + ((g >> 1) << 3);
    const int b_kb = (g & 1) << 3;

    float acc[4][4][4];
#pragma unroll
    for (int i = 0; i < 4; i++)
#pragma unroll
        for (int j = 0; j < 4; j++)
#pragma unroll
            for (int e = 0; e < 4; e++) acc[i][j][e] = 0.f;

    uint4 pa_h[2], pa_l[2], pb_h[2], pb_l[2];

    auto LOAD = [&](int k0) {
#pragma unroll
        for (int j = 0; j < 2; j++) {
            size_t oa = (size_t)(lrow + j * 64) * lda + k0 + lc16 * 8;
            size_t ob = (size_t)(lrow + j * 64) * ldb + k0 + lc16 * 8;
            pa_h[j] = *(const uint4*)(Ah_g + oa);
            pa_l[j] = *(const uint4*)(Al_g + oa);
            pb_h[j] = *(const uint4*)(Bh_g + ob);
            pb_l[j] = *(const uint4*)(Bl_g + ob);
        }
    };
    auto STORE = [&](int s) {
        char* p = dsm + s * 40960;
#pragma unroll
        for (int j = 0; j < 2; j++) {
            uint32_t so = (uint32_t)(lrow + j * 64) * 80 + lc16 * 16;
            *(uint4*)(p + 0     + so) = pa_h[j];
            *(uint4*)(p + 10240 + so) = pa_l[j];
            *(uint4*)(p + 20480 + so) = pb_h[j];
            *(uint4*)(p + 30720 + so) = pb_l[j];
        }
    };
    auto COMPUTE = [&](int s) {
        const uint32_t base = sb + (uint32_t)s * 40960u;
#pragma unroll
        for (int ks = 0; ks < 32; ks += 16) {
            uint32_t ah[16], bh[8];
#pragma unroll
            for (int i = 0; i < 4; i++)
                ldsm4(&ah[4 * i], base + (uint32_t)(wm + i * 16 + a_r) * 80 +
                                  (uint32_t)(ks + a_kb) * 2);
            ldsm4(&bh[0], base + 20480 + (uint32_t)(wn + b_r) * 80 +
                          (uint32_t)(ks + b_kb) * 2);
            ldsm4(&bh[4], base + 20480 + (uint32_t)(wn + 16 + b_r) * 80 +
                          (uint32_t)(ks + b_kb) * 2);
#pragma unroll
            for (int i = 0; i < 4; i++)
#pragma unroll
                for (int j = 0; j < 4; j++)
                    mma16816(acc[i][j], &ah[4 * i], &bh[2 * j]);
            uint32_t bl[8];
            ldsm4(&bl[0], base + 30720 + (uint32_t)(wn + b_r) * 80 +
                          (uint32_t)(ks + b_kb) * 2);
            ldsm4(&bl[4], base + 30720 + (uint32_t)(wn + 16 + b_r) * 80 +
                          (uint32_t)(ks + b_kb) * 2);
#pragma unroll
            for (int i = 0; i < 4; i++)
#pragma unroll
                for (int j = 0; j < 4; j++)
                    mma16816(acc[i][j], &ah[4 * i], &bl[2 * j]);
            uint32_t al[16];
#pragma unroll
            for (int i = 0; i < 4; i++)
                ldsm4(&al[4 * i], base + 10240 + (uint32_t)(wm + i * 16 + a_r) * 80 +
                                  (uint32_t)(ks + a_kb) * 2);
#pragma unroll
            for (int i = 0; i < 4; i++)
#pragma unroll
                for (int j = 0; j < 4; j++)
                    mma16816(acc[i][j], &al[4 * i], &bh[2 * j]);
        }
    };

    const int T = K >> 5;
    LOAD(0);
    STORE(0);
    __syncthreads();
    for (int t = 0; t < T; t++) {
        if (t + 1 < T) LOAD((t + 1) << 5);
        COMPUTE(t & 1);
        if (t + 1 < T) STORE((t + 1) & 1);
        __syncthreads();
    }

    // ------------------------------ epilogue --------------------------------
    const int rbase = blockIdx.y * 128 + wm;
    const int cbase = blockIdx.x * 128 + wn;
#pragma unroll
    for (int i = 0; i < 4; i++) {
#pragma unroll
        for (int j = 0; j < 4; j++) {
            int row0 = rbase + i * 16 + (lane >> 2);
            int col = cbase + j * 8 + ((lane & 3) << 1);
            float2 v0 = {acc[i][j][0], acc[i][j][1]};
            float2 v1 = {acc[i][j][2], acc[i][j][3]};
            if (BIAS) {
                float2 b2 = *(const float2*)(bias + col);
                v0.x += b2.x; v0.y += b2.y;
                v1.x += b2.x; v1.y += b2.y;
            }
            if (FOUT) {
                *(float2*)(C + (size_t)row0 * ldc + col) = v0;
                *(float2*)(C + (size_t)(row0 + 8) * ldc + col) = v1;
            }
            if (SPLITOUT) {
                __half h0, h1, l0, l1;
                split1(v0.x, h0, l0); split1(v0.y, h1, l1);
                *(uint32_t*)(Chi + (size_t)row0 * ldc + col) = pack2(h0, h1);
                *(uint32_t*)(Clo + (size_t)row0 * ldc + col) = pack2(l0, l1);
                split1(v1.x, h0, l0); split1(v1.y, h1, l1);
                *(uint32_t*)(Chi + (size_t)(row0 + 8) * ldc + col) = pack2(h0, h1);
                *(uint32_t*)(Clo + (size_t)(row0 + 8) * ldc + col) = pack2(l0, l1);
            }
        }
    }
}

// ----------------------- transpose + split to fp16 --------------------------
__global__ void __launch_bounds__(256)
transpose_split(const float* __restrict__ in, __half* __restrict__ hi,
                __half* __restrict__ lo, int ldin, int ldout)
{
    __shared__ float t[32][33];
    const int bx = blockIdx.x * 32, by = blockIdx.y * 32;
    const int x = threadIdx.x, y = threadIdx.y;
#pragma unroll
    for (int j = 0; j < 32; j += 8)
        t[y + j][x] = in[(size_t)(by + y + j) * ldin + bx + x];
    __syncthreads();
#pragma unroll
    for (int j = 0; j < 32; j += 8) {
        float v = t[x][y + j];
        __half h, l;
        split1(v, h, l);
        size_t o = (size_t)(bx + y + j) * ldout + by + x;
        hi[o] = h;
        lo[o] = l;
    }
}

// --------------------------- plain split to fp16 ----------------------------
__global__ void __launch_bounds__(256)
split_f16(const float* __restrict__ in, __half* __restrict__ hi,
          __half* __restrict__ lo, int n4)
{
    int i = blockIdx.x * 256 + threadIdx.x;
    if (i >= n4) return;
    float4 v = ((const float4*)in)[i];
    uint2 h, l;
    split4(v, h, l);
    ((uint2*)hi)[i] = h;
    ((uint2*)lo)[i] = l;
}

// -------------------- L2 normalize (per head) + split -----------------------
__global__ void __launch_bounds__(256)
l2norm_split(const float* __restrict__ src, __half* __restrict__ hi,
             __half* __restrict__ lo, int lds, int ldd, int nvec)
{
    int vec = blockIdx.x * 8 + (threadIdx.x >> 5);
    int lane = threadIdx.x & 31;
    if (vec >= nvec) return;
    int row = vec >> 3, h = vec & 7;
    const float* s = src + (size_t)row * lds + h * 128 + lane * 4;
    float4 v = *(const float4*)s;
    float ss = v.x * v.x + v.y * v.y + v.z * v.z + v.w * v.w;
#pragma unroll
    for (int o = 16; o; o >>= 1) ss += __shfl_xor_sync(0xffffffffu, ss, o);
    float inv = 1.0f / sqrtf(ss);
    float4 o4 = {v.x * inv, v.y * inv, v.z * inv, v.w * inv};
    uint2 hh, ll;
    split4(o4, hh, ll);
    size_t o = (size_t)row * ldd + h * 128 + lane * 4;
    *(uint2*)(hi + o) = hh;
    *(uint2*)(lo + o) = ll;
}

// ------------------------------ block reductions ----------------------------
static __device__ __forceinline__ float blockReduceMax(float v) {
    __shared__ float s[8];
#pragma unroll
    for (int o = 16; o; o >>= 1) v = fmaxf(v, __shfl_xor_sync(0xffffffffu, v, o));
    if ((threadIdx.x & 31) == 0) s[threadIdx.x >> 5] = v;
    __syncthreads();
    v = s[threadIdx.x & 7];
#pragma unroll
    for (int o = 4; o; o >>= 1) v = fmaxf(v, __shfl_xor_sync(0xffffffffu, v, o));
    __syncthreads();
    return v;
}
static __device__ __forceinline__ float blockReduceSum(float v) {
    __shared__ float s[8];
#pragma unroll
    for (int o = 16; o; o >>= 1) v += __shfl_xor_sync(0xffffffffu, v, o);
    if ((threadIdx.x & 31) == 0) s[threadIdx.x >> 5] = v;
    __syncthreads();
    v = s[threadIdx.x & 7];
#pragma unroll
    for (int o = 4; o; o >>= 1) v += __shfl_xor_sync(0xffffffffu, v, o);
    __syncthreads();
    return v;
}

// --------------------- softmax blend, write split attn ----------------------
__global__ void __launch_bounds__(256)
softmax_combine(const float* __restrict__ sc_cls, const float* __restrict__ sc_reg,
                const float* __restrict__ cls_score,
                __half* __restrict__ attn_h, __half* __restrict__ attn_l,
                float* __restrict__ asum)
{
    const int q = blockIdx.x;
    const int tid = threadIdx.x;
    float cs[8], accum[8];
#pragma unroll
    for (int j = 0; j < 8; j++) {
        cs[j] = cls_score[j * 256 + tid];
        accum[j] = 0.f;
    }
    for (int h = 0; h < 8; h++) {
        const float* pc = sc_cls + ((size_t)h * 512 + q) * 2048;
        const float* pr = sc_reg + ((size_t)h * 512 + q) * 2048;
        float c[8], r[8];
        float mc = -1e30f, mr = -1e30f;
#pragma unroll
        for (int j = 0; j < 8; j++) {
            int k = j * 256 + tid;
            c[j] = pc[k] * 25.0f * cs[j];
            r[j] = pr[k] * 25.0f;
            mc = fmaxf(mc, c[j]);
            mr = fmaxf(mr, r[j]);
        }
        mc = blockReduceMax(mc);
        mr = blockReduceMax(mr);
        float sc = 0.f, sr = 0.f;
#pragma unroll
        for (int j = 0; j < 8; j++) {
            c[j] = expf(c[j] - mc);
            r[j] = expf(r[j] - mr);
            sc += c[j];
            sr += r[j];
        }
        sc = blockReduceSum(sc);
        sr = blockReduceSum(sr);
        float ic = 0.5f / sc, ir = 0.5f / sr;
        size_t pb = ((size_t)h * 512 + q) * 2048;
#pragma unroll
        for (int j = 0; j < 8; j++) {
            float a = c[j] * ic + r[j] * ir;
            __half hh, ll;
            split1(a, hh, ll);
            attn_h[pb + j * 256 + tid] = hh;
            attn_l[pb + j * 256 + tid] = ll;
            accum[j] += a;
        }
    }
#pragma unroll
    for (int j = 0; j < 8; j++) asum[(size_t)q * 2048 + j * 256 + tid] = accum[j];
}

// ------------- masked renormalized second-round weights (split) -------------
__global__ void __launch_bounds__(256)
mask_renorm(const float* __restrict__ asum, const float* __restrict__ simc,
            const float* __restrict__ simr,
            __half* __restrict__ s2h, __half* __restrict__ s2l,
            __half* __restrict__ owh, __half* __restrict__ owl)
{
    const int q = blockIdx.x;
    const int tid = threadIdx.x;
    float a[8];
    float mx = -1e30f;
#pragma unroll
    for (int j = 0; j < 8; j++) {
        a[j] = asum[(size_t)q * 2048 + j * 256 + tid] * 0.125f;
        mx = fmaxf(mx, a[j]);
    }
    mx = blockReduceMax(mx);
    float sum = 0.f;
#pragma unroll
    for (int j = 0; j < 8; j++) {
        a[j] = expf(a[j] - mx);
        sum += a[j];
    }
    sum = blockReduceSum(sum);
    float inv = 1.0f / sum;
    float sm = 0.f;
#pragma unroll
    for (int j = 0; j < 8; j++) {
        int k = j * 256 + tid;
        float m = (simc[(size_t)q * 2048 + k] * 0.125f > 0.75f) ? 1.0f : 0.0f;
        a[j] = a[j] * inv * m;
        sm += a[j];
    }
    sm = blockReduceSum(sm);
    inv = 1.0f / sm;
    float so = 0.f;
    float o[8];
#pragma unroll
    for (int j = 0; j < 8; j++) {
        int k = j * 256 + tid;
        a[j] *= inv;
        __half hh, ll;
        split1(a[j], hh, ll);
        s2h[(size_t)q * 2048 + k] = hh;
        s2l[(size_t)q * 2048 + k] = ll;
        float m = (simr[(size_t)q * 2048 + k] * 0.125f > 0.99f) ? 1.0f : 0.0f;
        o[j] = a[j] * m;
        so += o[j];
    }
    so = blockReduceSum(so);
    inv = 1.0f / so;
#pragma unroll
    for (int j = 0; j < 8; j++) {
        float v = o[j] * inv;
        __half hh, ll;
        split1(v, hh, ll);
        owh[(size_t)q * 2048 + j * 256 + tid] = hh;
        owl[(size_t)q * 2048 + j * 256 + tid] = ll;
    }
}

// -------------------- copy x_ori into concat (split) ------------------------
__global__ void __launch_bounds__(256)
copy_xori(const float* __restrict__ kv, __half* __restrict__ xh,
          __half* __restrict__ xl)
{
    int idx = blockIdx.x * 256 + threadIdx.x;   // 512*256 float4s
    int q = idx >> 8;
    int c4 = idx & 255;
    size_t off = (size_t)q * 2048 + 1024 + (size_t)c4 * 4;
    float4 v = *(const float4*)(kv + off);
    uint2 h, l;
    split4(v, h, l);
    *(uint2*)(xh + off) = h;
    *(uint2*)(xl + off) = l;
}

// --------------------------------- launch -----------------------------------
extern "C" void kernel_launch(void* const* d_in, const int* in_sizes, int n_in,
                              void* d_out, int out_size)
{
    const float* x_cls     = (const float*)d_in[0];
    const float* x_reg     = (const float*)d_in[1];
    const float* cls_score = (const float*)d_in[2];
    const float* W_q_cls   = (const float*)d_in[4];
    const float* W_kv_cls  = (const float*)d_in[5];
    const float* W_q_reg   = (const float*)d_in[6];
    const float* W_kv_reg  = (const float*)d_in[7];
    const float* W_lin     = (const float*)d_in[8];
    const float* b_lin     = (const float*)d_in[9];
    const float* W_lin_reg = (const float*)d_in[10];
    const float* b_lin_reg = (const float*)d_in[11];
    float* out = (float*)d_out;

    float* F = nullptr;
    __half* Hp = nullptr;
    cudaGetSymbolAddress((void**)&F, g_scratch);
    cudaGetSymbolAddress((void**)&Hp, g_half);

    float* qc   = F + F_QC;
    float* qr   = F + F_QR;
    float* kvc  = F + F_KVC;
    float* kvr  = F + F_KVR;
    float* scc  = F + F_SCC;
    float* scr  = F + F_SCR;
    float* asum = F + F_ASUM;
    float* simc = F + F_SIMC;
    float* simr = F + F_SIMR;

    cudaFuncSetAttribute(hgemm<false, true, false>,
                         cudaFuncAttributeMaxDynamicSharedMemorySize, HG_SMEM);
    cudaFuncSetAttribute(hgemm<true, true, false>,
                         cudaFuncAttributeMaxDynamicSharedMemorySize, HG_SMEM);
    cudaFuncSetAttribute(hgemm<false, false, true>,
                         cudaFuncAttributeMaxDynamicSharedMemorySize, HG_SMEM);

    const long long HSTR = 512LL * 2048LL;
    float* out_reg = out + (size_t)512 * 3072;
    dim3 tb(32, 8);

    // 0) transpose+split weights: W[K,N] -> WT[N,K] fp16 planes
    transpose_split<<<dim3(32, 32), tb>>>(W_q_cls, Hp + HWQCH, Hp + HWQCL, 1024, 1024);
    transpose_split<<<dim3(32, 32), tb>>>(W_q_reg, Hp + HWQRH, Hp + HWQRL, 1024, 1024);
    transpose_split<<<dim3(64, 32), tb>>>(W_kv_cls, Hp + HWKCH, Hp + HWKCL, 2048, 1024);
    transpose_split<<<dim3(64, 32), tb>>>(W_kv_reg, Hp + HWKRH, Hp + HWKRL, 2048, 1024);
    transpose_split<<<dim3(64, 64), tb>>>(W_lin, Hp + HWLCH, Hp + HWLCL, 2048, 2048);
    transpose_split<<<dim3(64, 64), tb>>>(W_lin_reg, Hp + HWLRH, Hp + HWLRL, 2048, 2048);

    // 0b) split x
    split_f16<<<2048, 256>>>(x_cls, Hp + HXCH, Hp + HXCL, 2048 * 256);
    split_f16<<<2048, 256>>>(x_reg, Hp + HXRH, Hp + HXRL, 2048 * 256);

    // 1) projections (fp32 out; normalized + re-split downstream)
    hgemm<false, true, false><<<dim3(8, 4), 256, HG_SMEM>>>(
        Hp + HXCH, Hp + HXCL, Hp + HWQCH, Hp + HWQCL, nullptr,
        qc, nullptr, nullptr, 1024, 1024, 1024, 1024, 0, 0, 0);
    hgemm<false, true, false><<<dim3(16, 16), 256, HG_SMEM>>>(
        Hp + HXCH, Hp + HXCL, Hp + HWKCH, Hp + HWKCL, nullptr,
        kvc, nullptr, nullptr, 1024, 1024, 1024, 2048, 0, 0, 0);
    hgemm<false, true, false><<<dim3(8, 4), 256, HG_SMEM>>>(
        Hp + HXRH, Hp + HXRL, Hp + HWQRH, Hp + HWQRL, nullptr,
        qr, nullptr, nullptr, 1024, 1024, 1024, 1024, 0, 0, 0);
    hgemm<false, true, false><<<dim3(16, 16), 256, HG_SMEM>>>(
        Hp + HXRH, Hp + HXRL, Hp + HWKRH, Hp + HWKRL, nullptr,
        kvr, nullptr, nullptr, 1024, 1024, 1024, 2048, 0, 0, 0);

    // 2) L2 norm + split (q, k, v_n); transpose+split raw v
    l2norm_split<<<512, 256>>>(qc, Hp + HQCH, Hp + HQCL, 1024, 1024, 512 * 8);
    l2norm_split<<<512, 256>>>(qr, Hp + HQRH, Hp + HQRL, 1024, 1024, 512 * 8);
    l2norm_split<<<2048, 256>>>(kvc, Hp + HKCH, Hp + HKCL, 2048, 1024, 2048 * 8);
    l2norm_split<<<2048, 256>>>(kvr, Hp + HKRH, Hp + HKRL, 2048, 1024, 2048 * 8);
    l2norm_split<<<2048, 256>>>(kvc + 1024, Hp + HVNCH, Hp + HVNCL, 2048, 1024, 2048 * 8);
    l2norm_split<<<2048, 256>>>(kvr + 1024, Hp + HVNRH, Hp + HVNRL, 2048, 1024, 2048 * 8);
    transpose_split<<<dim3(32, 64), tb>>>(kvc + 1024, Hp + HVTCH, Hp + HVTCL, 2048, 2048);
    transpose_split<<<dim3(32, 64), tb>>>(kvr + 1024, Hp + HVTRH, Hp + HVTRL, 2048, 2048);

    // 3) attention scores per head (fp32 out)
    hgemm<false, true, false><<<dim3(16, 4, 8), 256, HG_SMEM>>>(
        Hp + HQCH, Hp + HQCL, Hp + HKCH, Hp + HKCL, nullptr,
        scc, nullptr, nullptr, 128, 1024, 1024, 2048, 128, 128, HSTR);
    hgemm<false, true, false><<<dim3(16, 4, 8), 256, HG_SMEM>>>(
        Hp + HQRH, Hp + HQRL, Hp + HKRH, Hp + HKRL, nullptr,
        scr, nullptr, nullptr, 128, 1024, 1024, 2048, 128, 128, HSTR);

    // 4) head-summed v-similarities (one full-width NT GEMM each)
    hgemm<false, true, false><<<dim3(16, 4), 256, HG_SMEM>>>(
        Hp + HVNCH, Hp + HVNCL, Hp + HVNCH, Hp + HVNCL, nullptr,
        simc, nullptr, nullptr, 1024, 1024, 1024, 2048, 0, 0, 0);
    hgemm<false, true, false><<<dim3(16, 4), 256, HG_SMEM>>>(
        Hp + HVNRH, Hp + HVNRL, Hp + HVNRH, Hp + HVNRL, nullptr,
        simr, nullptr, nullptr, 1024, 1024, 1024, 2048, 0, 0, 0);

    // 5) softmax blend -> split attn + asum
    softmax_combine<<<512, 256>>>(scc, scr, cls_score,
                                  Hp + HATH, Hp + HATL, asum);

    // 6) x = attn @ v per head -> split concat planes (cols [0,1024))
    hgemm<false, false, true><<<dim3(1, 4, 8), 256, HG_SMEM>>>(
        Hp + HATH, Hp + HATL, Hp + HVTCH, Hp + HVTCL, nullptr,
        nullptr, Hp + HXCCH, Hp + HXCCL, 2048, 2048, 2048, 2048,
        HSTR, 128LL * 2048, 128);
    hgemm<false, false, true><<<dim3(1, 4, 8), 256, HG_SMEM>>>(
        Hp + HATH, Hp + HATL, Hp + HVTRH, Hp + HVTRL, nullptr,
        nullptr, Hp + HXCRH, Hp + HXCRL, 2048, 2048, 2048, 2048,
        HSTR, 128LL * 2048, 128);

    // 7) x_ori into concat cols [1024,2048) (split)
    copy_xori<<<512, 256>>>(kvc, Hp + HXCCH, Hp + HXCCL);
    copy_xori<<<512, 256>>>(kvr, Hp + HXCRH, Hp + HXCRL);

    // 8) second-round masked weights (split)
    mask_renorm<<<512, 256>>>(asum, simc, simr,
                              Hp + HS2H, Hp + HS2L, Hp + HOWH, Hp + HOWL);

    // 9) output linears -> out cols [1024,3072)
    hgemm<true, true, false><<<dim3(16, 4), 256, HG_SMEM>>>(
        Hp + HXCCH, Hp + HXCCL, Hp + HWLCH, Hp + HWLCL, b_lin,
        out + 1024, nullptr, nullptr, 2048, 2048, 2048, 3072, 0, 0, 0);
    hgemm<true, true, false><<<dim3(16, 4), 256, HG_SMEM>>>(
        Hp + HXCRH, Hp + HXCRL, Hp + HWLRH, Hp + HWLRL, b_lin_reg,
        out_reg + 1024, nullptr, nullptr, 2048, 2048, 2048, 3072, 0, 0, 0);

    // 10) averaged support features -> out cols [0,1024)
    hgemm<false, true, false><<<dim3(8, 4), 256, HG_SMEM>>>(
        Hp + HS2H, Hp + HS2L, Hp + HVTCH, Hp + HVTCL, nullptr,
        out, nullptr, nullptr, 2048, 2048, 2048, 3072, 0, 0, 0);
    hgemm<false, true, false><<<dim3(8, 4), 256, HG_SMEM>>>(
        Hp + HOWH, Hp + HOWL, Hp + HVTRH, Hp + HVTRL, nullptr,
        out_reg, nullptr, nullptr, 2048, 2048, 2048, 3072, 0, 0, 0);
}

// round 4
// speedup vs baseline: 4.5335x; 1.5304x over previous
#include <cuda_runtime.h>
#include <cuda_fp16.h>
#include <cstdint>

// ===========================================================================
// Fixed shapes: B=1, N1=512, N2=2048, C=1024, H=8, hd=128
// All GEMMs: mma.sync m16n8k16 fp16, 3-term hi/lo split (err ~2^-21).
// Round 4: branch/head batching via blockIdx.z decomposition + TM=64 tiles
// for M=512 GEMMs -> full-chip occupancy, 7 GEMM launches total.
// ===========================================================================

constexpr size_t Mi = 1024 * 1024;

// ------------------------- fp32 scratch layout ------------------------------
constexpr size_t F_QC   = 0;                 // [512,1024] x2 branches
constexpr size_t F_QR   = F_QC   + Mi / 2;
constexpr size_t F_KVC  = F_QR   + Mi / 2;   // [2048,2048] x2
constexpr size_t F_KVR  = F_KVC  + 4 * Mi;
constexpr size_t F_SCC  = F_KVR  + 4 * Mi;   // [8,512,2048] x2
constexpr size_t F_SCR  = F_SCC  + 8 * Mi;
constexpr size_t F_ASUM = F_SCR  + 8 * Mi;   // [512,2048]
constexpr size_t F_SIMC = F_ASUM + Mi;
constexpr size_t F_SIMR = F_SIMC + Mi;
constexpr size_t F_BIAS = F_SIMR + Mi;       // [2,2048]
constexpr size_t F_TOTAL = F_BIAS + 4096;
__device__ float g_scratch[F_TOTAL];

// ------------------------- fp16 plane layout --------------------------------
// For every tensor: hi/lo planes adjacent, cls/reg twins at constant stride.
constexpr size_t HXCH  = 0;                  // x [2048,1024]: XCH,XCL,XRH,XRL
constexpr size_t HXCL  = HXCH  + 2 * Mi;
constexpr size_t HXRH  = HXCL  + 2 * Mi;
constexpr size_t HXRL  = HXRH  + 2 * Mi;
constexpr size_t HWQCH = HXRL  + 2 * Mi;     // WqT [1024,1024]
constexpr size_t HWQCL = HWQCH + 1 * Mi;
constexpr size_t HWQRH = HWQCL + 1 * Mi;
constexpr size_t HWQRL = HWQRH + 1 * Mi;
constexpr size_t HWKCH = HWQRL + 1 * Mi;     // WkvT [2048,1024]
constexpr size_t HWKCL = HWKCH + 2 * Mi;
constexpr size_t HWKRH = HWKCL + 2 * Mi;
constexpr size_t HWKRL = HWKRH + 2 * Mi;
constexpr size_t HWLCH = HWKRL + 2 * Mi;     // WlinT [2048,2048]
constexpr size_t HWLCL = HWLCH + 4 * Mi;
constexpr size_t HWLRH = HWLCL + 4 * Mi;
constexpr size_t HWLRL = HWLRH + 4 * Mi;
constexpr size_t HQCH  = HWLRL + 4 * Mi;     // q norm [512,1024]
constexpr size_t HQCL  = HQCH  + Mi / 2;
constexpr size_t HQRH  = HQCL  + Mi / 2;
constexpr size_t HQRL  = HQRH  + Mi / 2;
constexpr size_t HKCH  = HQRL  + Mi / 2;     // k norm [2048,1024]
constexpr size_t HKCL  = HKCH  + 2 * Mi;
constexpr size_t HKRH  = HKCL  + 2 * Mi;
constexpr size_t HKRL  = HKRH  + 2 * Mi;
constexpr size_t HVNCH = HKRL  + 2 * Mi;     // v norm [2048,1024]
constexpr size_t HVNCL = HVNCH + 2 * Mi;
constexpr size_t HVNRH = HVNCL + 2 * Mi;
constexpr size_t HVNRL = HVNRH + 2 * Mi;
constexpr size_t HVTCH = HVNRL + 2 * Mi;     // vT [1024,2048]
constexpr size_t HVTCL = HVTCH + 2 * Mi;
constexpr size_t HVTRH = HVTCL + 2 * Mi;
constexpr size_t HVTRL = HVTRH + 2 * Mi;
constexpr size_t HATH  = HVTRL + 2 * Mi;     // attn [8,512,2048] (shared)
constexpr size_t HATL  = HATH  + 8 * Mi;
constexpr size_t HS2H  = HATL  + 8 * Mi;     // s2 / ow [512,2048]
constexpr size_t HS2L  = HS2H  + Mi;
constexpr size_t HOWH  = HS2L  + Mi;
constexpr size_t HOWL  = HOWH  + Mi;
constexpr size_t HXCCH = HOWL  + Mi;         // concat [512,2048]
constexpr size_t HXCCL = HXCCH + Mi;
constexpr size_t HXCRH = HXCCL + Mi;
constexpr size_t HXCRL = HXCRH + Mi;
constexpr size_t H_TOTAL = HXCRL + Mi;
__device__ __half g_half[H_TOTAL];

// ----------------------------- helpers --------------------------------------
__device__ __forceinline__ uint32_t smem_u32(const void* p) {
    uint32_t a;
    asm("{ .reg .u64 t; cvta.to.shared.u64 t, %1; cvt.u32.u64 %0, t; }"
        : "=r"(a) : "l"(p));
    return a;
}
__device__ __forceinline__ uint32_t pack2(__half a, __half b) {
    __half2 h = __halves2half2(a, b);
    return *(uint32_t*)&h;
}
__device__ __forceinline__ void split1(float x, __half& h, __half& l) {
    h = __float2half_rn(x);
    l = __float2half_rn(x - __half2float(h));
}
__device__ __forceinline__ void split4(float4 v, uint2& hi, uint2& lo) {
    __half h0, h1, h2, h3, l0, l1, l2, l3;
    split1(v.x, h0, l0); split1(v.y, h1, l1);
    split1(v.z, h2, l2); split1(v.w, h3, l3);
    hi.x = pack2(h0, h1); hi.y = pack2(h2, h3);
    lo.x = pack2(l0, l1); lo.y = pack2(l2, l3);
}
__device__ __forceinline__ void ldsm4(uint32_t* r, uint32_t addr) {
    asm volatile("ldmatrix.sync.aligned.m8n8.x4.shared.b16 {%0,%1,%2,%3}, [%4];"
                 : "=r"(r[0]), "=r"(r[1]), "=r"(r[2]), "=r"(r[3]) : "r"(addr));
}
__device__ __forceinline__ void mma16816(float* d, const uint32_t* a, const uint32_t* b) {
    asm volatile("mma.sync.aligned.m16n8k16.row.col.f32.f16.f16.f32 "
                 "{%0,%1,%2,%3}, {%4,%5,%6,%7}, {%8,%9}, {%0,%1,%2,%3};"
                 : "+f"(d[0]), "+f"(d[1]), "+f"(d[2]), "+f"(d[3])
                 : "r"(a[0]), "r"(a[1]), "r"(a[2]), "r"(a[3]),
                   "r"(b[0]), "r"(b[1]));
}

// ------------------------------- hgemm (NT) ----------------------------------
// C[M,N] = (Ah+Al)[M,K]*(Bh+Bl)[N,K]^T (3-term). CTA tile TMx128x32, 8 warps.
// TM=128: warp 64x32; TM=64: warp 32x32. blockIdx.z -> (z1 = z%z1n, z2 = z/z1n)
// offsets per operand: z1*s1 + z2*s2.
template <int TM, bool BIAS, bool FOUT, bool SPLITOUT>
__global__ void __launch_bounds__(256)
hgemm(const __half* __restrict__ Ah_g, const __half* __restrict__ Al_g,
      const __half* __restrict__ Bh_g, const __half* __restrict__ Bl_g,
      const float* __restrict__ bias,
      float* C, __half* Chi, __half* Clo,
      int K, int lda, int ldb, int ldc, int z1n,
      long long a_s1, long long a_s2, long long b_s1, long long b_s2,
      long long c_s1, long long c_s2, long long bias_s)
{
    constexpr int ASZ = TM * 80;            // bytes per A plane
    constexpr int STAGE = 2 * ASZ + 20480;  // + 2 B planes (128*80 each)
    constexpr int AJ = TM / 64;
    constexpr int WM = (TM == 128) ? 64 : 32;
    constexpr int MI = WM / 16;

    extern __shared__ char dsm[];
    const uint32_t sb = smem_u32(dsm);
    const int tid = threadIdx.x;

    const int z1 = blockIdx.z % z1n, z2 = blockIdx.z / z1n;
    const long long aoff = (long long)z1 * a_s1 + (long long)z2 * a_s2 +
                           (long long)blockIdx.y * TM * lda;
    const long long boff = (long long)z1 * b_s1 + (long long)z2 * b_s2 +
                           (long long)blockIdx.x * 128 * ldb;
    const long long coff = (long long)z1 * c_s1 + (long long)z2 * c_s2;
    Ah_g += aoff; Al_g += aoff;
    Bh_g += boff; Bl_g += boff;
    if (FOUT) C += coff;
    if (SPLITOUT) { Chi += coff; Clo += coff; }
    if (BIAS) bias += z1 * bias_s;

    const int lrow = tid >> 2;        // 0..63
    const int lc16 = tid & 3;         // 16B chunk within 64B k-row

    const int lane = tid & 31, w = tid >> 5;
    const int wm = (w >> 2) * WM;
    const int wn = (w & 3) << 5;
    const int g = lane >> 3, r = lane & 7;
    const int a_r  = r + ((g & 1) << 3);
    const int a_kb = (g >> 1) << 3;
    const int b_r  = r + ((g >> 1) << 3);
    const int b_kb = (g & 1) << 3;

    float acc[MI][4][4];
#pragma unroll
    for (int i = 0; i < MI; i++)
#pragma unroll
        for (int j = 0; j < 4; j++)
#pragma unroll
            for (int e = 0; e < 4; e++) acc[i][j][e] = 0.f;

    uint4 pa_h[AJ], pa_l[AJ], pb_h[2], pb_l[2];

    auto LOAD = [&](int k0) {
#pragma unroll
        for (int j = 0; j < AJ; j++) {
            size_t oa = (size_t)(lrow + j * 64) * lda + k0 + lc16 * 8;
            pa_h[j] = *(const uint4*)(Ah_g + oa);
            pa_l[j] = *(const uint4*)(Al_g + oa);
        }
#pragma unroll
        for (int j = 0; j < 2; j++) {
            size_t ob = (size_t)(lrow + j * 64) * ldb + k0 + lc16 * 8;
            pb_h[j] = *(const uint4*)(Bh_g + ob);
            pb_l[j] = *(const uint4*)(Bl_g + ob);
        }
    };
    auto STORE = [&](int s) {
        char* p = dsm + s * STAGE;
#pragma unroll
        for (int j = 0; j < AJ; j++) {
            uint32_t so = (uint32_t)(lrow + j * 64) * 80 + lc16 * 16;
            *(uint4*)(p + so) = pa_h[j];
            *(uint4*)(p + ASZ + so) = pa_l[j];
        }
#pragma unroll
        for (int j = 0; j < 2; j++) {
            uint32_t so = (uint32_t)(lrow + j * 64) * 80 + lc16 * 16;
            *(uint4*)(p + 2 * ASZ + so) = pb_h[j];
            *(uint4*)(p + 2 * ASZ + 10240 + so) = pb_l[j];
        }
    };
    auto COMPUTE = [&](int s) {
        const uint32_t base = sb + (uint32_t)s * STAGE;
#pragma unroll
        for (int ks = 0; ks < 32; ks += 16) {
            uint32_t ah[4 * MI], bh[8];
#pragma unroll
            for (int i = 0; i < MI; i++)
                ldsm4(&ah[4 * i], base + (uint32_t)(wm + i * 16 + a_r) * 80 +
                                  (uint32_t)(ks + a_kb) * 2);
            ldsm4(&bh[0], base + 2 * ASZ + (uint32_t)(wn + b_r) * 80 +
                          (uint32_t)(ks + b_kb) * 2);
            ldsm4(&bh[4], base + 2 * ASZ + (uint32_t)(wn + 16 + b_r) * 80 +
                          (uint32_t)(ks + b_kb) * 2);
#pragma unroll
            for (int i = 0; i < MI; i++)
#pragma unroll
                for (int j = 0; j < 4; j++)
                    mma16816(acc[i][j], &ah[4 * i], &bh[2 * j]);
            uint32_t bl[8];
            ldsm4(&bl[0], base + 2 * ASZ + 10240 + (uint32_t)(wn + b_r) * 80 +
                          (uint32_t)(ks + b_kb) * 2);
            ldsm4(&bl[4], base + 2 * ASZ + 10240 + (uint32_t)(wn + 16 + b_r) * 80 +
                          (uint32_t)(ks + b_kb) * 2);
#pragma unroll
            for (int i = 0; i < MI; i++)
#pragma unroll
                for (int j = 0; j < 4; j++)
                    mma16816(acc[i][j], &ah[4 * i], &bl[2 * j]);
            uint32_t al[4 * MI];
#pragma unroll
            for (int i = 0; i < MI; i++)
                ldsm4(&al[4 * i], base + ASZ + (uint32_t)(wm + i * 16 + a_r) * 80 +
                                  (uint32_t)(ks + a_kb) * 2);
#pragma unroll
            for (int i = 0; i < MI; i++)
#pragma unroll
                for (int j = 0; j < 4; j++)
                    mma16816(acc[i][j], &al[4 * i], &bh[2 * j]);
        }
    };

    const int T = K >> 5;
    LOAD(0);
    STORE(0);
    __syncthreads();
    for (int t = 0; t < T; t++) {
        if (t + 1 < T) LOAD((t + 1) << 5);
        COMPUTE(t & 1);
        if (t + 1 < T) STORE((t + 1) & 1);
        __syncthreads();
    }

    // ------------------------------ epilogue ---------------------------------
    const int rbase = blockIdx.y * TM + wm;
    const int cbase = blockIdx.x * 128 + wn;
#pragma unroll
    for (int i = 0; i < MI; i++) {
#pragma unroll
        for (int j = 0; j < 4; j++) {
            int row0 = rbase + i * 16 + (lane >> 2);
            int col = cbase + j * 8 + ((lane & 3) << 1);
            float2 v0 = {acc[i][j][0], acc[i][j][1]};
            float2 v1 = {acc[i][j][2], acc[i][j][3]};
            if (BIAS) {
                float2 b2 = *(const float2*)(bias + col);
                v0.x += b2.x; v0.y += b2.y;
                v1.x += b2.x; v1.y += b2.y;
            }
            if (FOUT) {
                *(float2*)(C + (size_t)row0 * ldc + col) = v0;
                *(float2*)(C + (size_t)(row0 + 8) * ldc + col) = v1;
            }
            if (SPLITOUT) {
                __half h0, h1, l0, l1;
                split1(v0.x, h0, l0); split1(v0.y, h1, l1);
                *(uint32_t*)(Chi + (size_t)row0 * ldc + col) = pack2(h0, h1);
                *(uint32_t*)(Clo + (size_t)row0 * ldc + col) = pack2(l0, l1);
                split1(v1.x, h0, l0); split1(v1.y, h1, l1);
                *(uint32_t*)(Chi + (size_t)(row0 + 8) * ldc + col) = pack2(h0, h1);
                *(uint32_t*)(Clo + (size_t)(row0 + 8) * ldc + col) = pack2(l0, l1);
            }
        }
    }
}

// ----------------------- transpose + split to fp16 ---------------------------
__global__ void __launch_bounds__(256)
transpose_split(const float* __restrict__ in, __half* __restrict__ hi,
                __half* __restrict__ lo, int ldin, int ldout)
{
    __shared__ float t[32][33];
    const int bx = blockIdx.x * 32, by = blockIdx.y * 32;
    const int x = threadIdx.x, y = threadIdx.y;
#pragma unroll
    for (int j = 0; j < 32; j += 8)
        t[y + j][x] = in[(size_t)(by + y + j) * ldin + bx + x];
    __syncthreads();
#pragma unroll
    for (int j = 0; j < 32; j += 8) {
        float v = t[x][y + j];
        __half h, l;
        split1(v, h, l);
        size_t o = (size_t)(bx + y + j) * ldout + by + x;
        hi[o] = h;
        lo[o] = l;
    }
}

// --------------------------- plain split to fp16 -----------------------------
__global__ void __launch_bounds__(256)
split_f16(const float* __restrict__ in, __half* __restrict__ hi,
          __half* __restrict__ lo, int n4)
{
    int i = blockIdx.x * 256 + threadIdx.x;
    if (i >= n4) return;
    float4 v = ((const float4*)in)[i];
    uint2 h, l;
    split4(v, h, l);
    ((uint2*)hi)[i] = h;
    ((uint2*)lo)[i] = l;
}

// -------------------- L2 normalize (per head) + split -------------------------
__global__ void __launch_bounds__(256)
l2norm_split(const float* __restrict__ src, __half* __restrict__ hi,
             __half* __restrict__ lo, int lds, int ldd, int nvec)
{
    int vec = blockIdx.x * 8 + (threadIdx.x >> 5);
    int lane = threadIdx.x & 31;
    if (vec >= nvec) return;
    int row = vec >> 3, h = vec & 7;
    const float* s = src + (size_t)row * lds + h * 128 + lane * 4;
    float4 v = *(const float4*)s;
    float ss = v.x * v.x + v.y * v.y + v.z * v.z + v.w * v.w;
#pragma unroll
    for (int o = 16; o; o >>= 1) ss += __shfl_xor_sync(0xffffffffu, ss, o);
    float inv = 1.0f / sqrtf(ss);
    float4 o4 = {v.x * inv, v.y * inv, v.z * inv, v.w * inv};
    uint2 hh, ll;
    split4(o4, hh, ll);
    size_t o = (size_t)row * ldd + h * 128 + lane * 4;
    *(uint2*)(hi + o) = hh;
    *(uint2*)(lo + o) = ll;
}

// ------------------------------ block reductions -----------------------------
static __device__ __forceinline__ float blockReduceMax(float v) {
    __shared__ float s[8];
#pragma unroll
    for (int o = 16; o; o >>= 1) v = fmaxf(v, __shfl_xor_sync(0xffffffffu, v, o));
    if ((threadIdx.x & 31) == 0) s[threadIdx.x >> 5] = v;
    __syncthreads();
    v = s[threadIdx.x & 7];
#pragma unroll
    for (int o = 4; o; o >>= 1) v = fmaxf(v, __shfl_xor_sync(0xffffffffu, v, o));
    __syncthreads();
    return v;
}
static __device__ __forceinline__ float blockReduceSum(float v) {
    __shared__ float s[8];
#pragma unroll
    for (int o = 16; o; o >>= 1) v += __shfl_xor_sync(0xffffffffu, v, o);
    if ((threadIdx.x & 31) == 0) s[threadIdx.x >> 5] = v;
    __syncthreads();
    v = s[threadIdx.x & 7];
#pragma unroll
    for (int o = 4; o; o >>= 1) v += __shfl_xor_sync(0xffffffffu, v, o);
    __syncthreads();
    return v;
}

// --------------------- softmax blend, write split attn -----------------------
__global__ void __launch_bounds__(256)
softmax_combine(const float* __restrict__ sc_cls, const float* __restrict__ sc_reg,
                const float* __restrict__ cls_score,
                __half* __restrict__ attn_h, __half* __restrict__ attn_l,
                float* __restrict__ asum)
{
    const int q = blockIdx.x;
    const int tid = threadIdx.x;
    float cs[8], accum[8];
#pragma unroll
    for (int j = 0; j < 8; j++) {
        cs[j] = cls_score[j * 256 + tid];
        accum[j] = 0.f;
    }
    for (int h = 0; h < 8; h++) {
        const float* pc = sc_cls + ((size_t)h * 512 + q) * 2048;
        const float* pr = sc_reg + ((size_t)h * 512 + q) * 2048;
        float c[8], r[8];
        float mc = -1e30f, mr = -1e30f;
#pragma unroll
        for (int j = 0; j < 8; j++) {
            int k = j * 256 + tid;
            c[j] = pc[k] * 25.0f * cs[j];
            r[j] = pr[k] * 25.0f;
            mc = fmaxf(mc, c[j]);
            mr = fmaxf(mr, r[j]);
        }
        mc = blockReduceMax(mc);
        mr = blockReduceMax(mr);
        float sc = 0.f, sr = 0.f;
#pragma unroll
        for (int j = 0; j < 8; j++) {
            c[j] = expf(c[j] - mc);
            r[j] = expf(r[j] - mr);
            sc += c[j];
            sr += r[j];
        }
        sc = blockReduceSum(sc);
        sr = blockReduceSum(sr);
        float ic = 0.5f / sc, ir = 0.5f / sr;
        size_t pb = ((size_t)h * 512 + q) * 2048;
#pragma unroll
        for (int j = 0; j < 8; j++) {
            float a = c[j] * ic + r[j] * ir;
            __half hh, ll;
            split1(a, hh, ll);
            attn_h[pb + j * 256 + tid] = hh;
            attn_l[pb + j * 256 + tid] = ll;
            accum[j] += a;
        }
    }
#pragma unroll
    for (int j = 0; j < 8; j++) asum[(size_t)q * 2048 + j * 256 + tid] = accum[j];
}

// ------------- masked renormalized second-round weights (split) --------------
__global__ void __launch_bounds__(256)
mask_renorm(const float* __restrict__ asum, const float* __restrict__ simc,
            const float* __restrict__ simr,
            __half* __restrict__ s2h, __half* __restrict__ s2l,
            __half* __restrict__ owh, __half* __restrict__ owl)
{
    const int q = blockIdx.x;
    const int tid = threadIdx.x;
    float a[8];
    float mx = -1e30f;
#pragma unroll
    for (int j = 0; j < 8; j++) {
        a[j] = asum[(size_t)q * 2048 + j * 256 + tid] * 0.125f;
        mx = fmaxf(mx, a[j]);
    }
    mx = blockReduceMax(mx);
    float sum = 0.f;
#pragma unroll
    for (int j = 0; j < 8; j++) {
        a[j] = expf(a[j] - mx);
        sum += a[j];
    }
    sum = blockReduceSum(sum);
    float inv = 1.0f / sum;
    float sm = 0.f;
#pragma unroll
    for (int j = 0; j < 8; j++) {
        int k = j * 256 + tid;
        float m = (simc[(size_t)q * 2048 + k] * 0.125f > 0.75f) ? 1.0f : 0.0f;
        a[j] = a[j] * inv * m;
        sm += a[j];
    }
    sm = blockReduceSum(sm);
    inv = 1.0f / sm;
    float so = 0.f;
    float o[8];
#pragma unroll
    for (int j = 0; j < 8; j++) {
        int k = j * 256 + tid;
        a[j] *= inv;
        __half hh, ll;
        split1(a[j], hh, ll);
        s2h[(size_t)q * 2048 + k] = hh;
        s2l[(size_t)q * 2048 + k] = ll;
        float m = (simr[(size_t)q * 2048 + k] * 0.125f > 0.99f) ? 1.0f : 0.0f;
        o[j] = a[j] * m;
        so += o[j];
    }
    so = blockReduceSum(so);
    inv = 1.0f / so;
#pragma unroll
    for (int j = 0; j < 8; j++) {
        float v = o[j] * inv;
        __half hh, ll;
        split1(v, hh, ll);
        owh[(size_t)q * 2048 + j * 256 + tid] = hh;
        owl[(size_t)q * 2048 + j * 256 + tid] = ll;
    }
}

// -------------------- copy x_ori into concat (split) -------------------------
// z picks branch: kv + z*4Mi, planes + z*2Mi
__global__ void __launch_bounds__(256)
copy_xori(const float* __restrict__ kv, __half* __restrict__ xh,
          __half* __restrict__ xl)
{
    int z = blockIdx.y;
    kv += (size_t)z * 4 * Mi;
    xh += (size_t)z * 2 * Mi;
    xl += (size_t)z * 2 * Mi;
    int idx = blockIdx.x * 256 + threadIdx.x;
    int q = idx >> 8;
    int c4 = idx & 255;
    size_t off = (size_t)q * 2048 + 1024 + (size_t)c4 * 4;
    float4 v = *(const float4*)(kv + off);
    uint2 h, l;
    split4(v, h, l);
    *(uint2*)(xh + off) = h;
    *(uint2*)(xl + off) = l;
}

// ------------------------------ bias copy ------------------------------------
__global__ void copy_bias(const float* __restrict__ b0, const float* __restrict__ b1,
                          float* __restrict__ dst)
{
    int i = blockIdx.x * 256 + threadIdx.x;
    if (i < 2048) { dst[i] = b0[i]; dst[2048 + i] = b1[i]; }
}

// --------------------------------- launch ------------------------------------
extern "C" void kernel_launch(void* const* d_in, const int* in_sizes, int n_in,
                              void* d_out, int out_size)
{
    const float* x_cls     = (const float*)d_in[0];
    const float* x_reg     = (const float*)d_in[1];
    const float* cls_score = (const float*)d_in[2];
    const float* W_q_cls   = (const float*)d_in[4];
    const float* W_kv_cls  = (const float*)d_in[5];
    const float* W_q_reg   = (const float*)d_in[6];
    const float* W_kv_reg  = (const float*)d_in[7];
    const float* W_lin     = (const float*)d_in[8];
    const float* b_lin     = (const float*)d_in[9];
    const float* W_lin_reg = (const float*)d_in[10];
    const float* b_lin_reg = (const float*)d_in[11];
    float* out = (float*)d_out;

    float* F = nullptr;
    __half* Hp = nullptr;
    cudaGetSymbolAddress((void**)&F, g_scratch);
    cudaGetSymbolAddress((void**)&Hp, g_half);

    float* qc   = F + F_QC;
    float* kvc  = F + F_KVC;
    float* scc  = F + F_SCC;
    float* scr  = F + F_SCR;
    float* asum = F + F_ASUM;
    float* simc = F + F_SIMC;
    float* simr = F + F_SIMR;
    float* bias2 = F + F_BIAS;

    constexpr int SM128 = 2 * (2 * 128 * 80 + 20480);  // 81920
    constexpr int SM64  = 2 * (2 * 64 * 80 + 20480);   // 61440
    cudaFuncSetAttribute(hgemm<128, false, true, false>,
                         cudaFuncAttributeMaxDynamicSharedMemorySize, SM128);
    cudaFuncSetAttribute(hgemm<64, false, true, false>,
                         cudaFuncAttributeMaxDynamicSharedMemorySize, SM64);
    cudaFuncSetAttribute(hgemm<64, true, true, false>,
                         cudaFuncAttributeMaxDynamicSharedMemorySize, SM64);
    cudaFuncSetAttribute(hgemm<64, false, false, true>,
                         cudaFuncAttributeMaxDynamicSharedMemorySize, SM64);

    dim3 tb(32, 8);
    const long long OSTR = 512LL * 3072;   // out branch stride

    // 0) transpose+split weights; split x; copy biases contiguous
    transpose_split<<<dim3(32, 32), tb>>>(W_q_cls, Hp + HWQCH, Hp + HWQCL, 1024, 1024);
    transpose_split<<<dim3(32, 32), tb>>>(W_q_reg, Hp + HWQRH, Hp + HWQRL, 1024, 1024);
    transpose_split<<<dim3(64, 32), tb>>>(W_kv_cls, Hp + HWKCH, Hp + HWKCL, 2048, 1024);
    transpose_split<<<dim3(64, 32), tb>>>(W_kv_reg, Hp + HWKRH, Hp + HWKRL, 2048, 1024);
    transpose_split<<<dim3(64, 64), tb>>>(W_lin, Hp + HWLCH, Hp + HWLCL, 2048, 2048);
    transpose_split<<<dim3(64, 64), tb>>>(W_lin_reg, Hp + HWLRH, Hp + HWLRL, 2048, 2048);
    split_f16<<<2048, 256>>>(x_cls, Hp + HXCH, Hp + HXCL, 2048 * 256);
    split_f16<<<2048, 256>>>(x_reg, Hp + HXRH, Hp + HXRL, 2048 * 256);
    copy_bias<<<8, 256>>>(b_lin, b_lin_reg, bias2);

    // 1) q projections, both branches (z=branch): M=512,N=1024,K=1024
    hgemm<64, false, true, false><<<dim3(8, 8, 2), 256, SM64>>>(
        Hp + HXCH, Hp + HXCL, Hp + HWQCH, Hp + HWQCL, nullptr,
        qc, nullptr, nullptr, 1024, 1024, 1024, 1024,
        2, 4 * Mi, 0, 2 * Mi, 0, Mi / 2, 0, 0);
    // kv projections: M=2048,N=2048,K=1024
    hgemm<128, false, true, false><<<dim3(16, 16, 2), 256, SM128>>>(
        Hp + HXCH, Hp + HXCL, Hp + HWKCH, Hp + HWKCL, nullptr,
        kvc, nullptr, nullptr, 1024, 1024, 1024, 2048,
        2, 4 * Mi, 0, 4 * Mi, 0, 4 * Mi, 0, 0);

    // 2) L2 norms + split; transpose+split raw v
    l2norm_split<<<512, 256>>>(qc, Hp + HQCH, Hp + HQCL, 1024, 1024, 512 * 8);
    l2norm_split<<<512, 256>>>(qc + Mi / 2, Hp + HQRH, Hp + HQRL, 1024, 1024, 512 * 8);
    l2norm_split<<<2048, 256>>>(kvc, Hp + HKCH, Hp + HKCL, 2048, 1024, 2048 * 8);
    l2norm_split<<<2048, 256>>>(kvc + 4 * Mi, Hp + HKRH, Hp + HKRL, 2048, 1024, 2048 * 8);
    l2norm_split<<<2048, 256>>>(kvc + 1024, Hp + HVNCH, Hp + HVNCL, 2048, 1024, 2048 * 8);
    l2norm_split<<<2048, 256>>>(kvc + 4 * Mi + 1024, Hp + HVNRH, Hp + HVNRL, 2048, 1024, 2048 * 8);
    transpose_split<<<dim3(32, 64), tb>>>(kvc + 1024, Hp + HVTCH, Hp + HVTCL, 2048, 2048);
    transpose_split<<<dim3(32, 64), tb>>>(kvc + 4 * Mi + 1024, Hp + HVTRH, Hp + HVTRL, 2048, 2048);

    // 3) scores: z = branch*8 + head (z1=head, z2=branch). M=512,N=2048,K=128
    hgemm<64, false, true, false><<<dim3(16, 8, 16), 256, SM64>>>(
        Hp + HQCH, Hp + HQCL, Hp + HKCH, Hp + HKCL, nullptr,
        scc, nullptr, nullptr, 128, 1024, 1024, 2048,
        8, 128, Mi, 128, 4 * Mi, Mi, 8 * Mi, 0);

    // 4) v-sims: M=512,N=2048,K=1024, z=branch
    hgemm<64, false, true, false><<<dim3(16, 8, 2), 256, SM64>>>(
        Hp + HVNCH, Hp + HVNCL, Hp + HVNCH, Hp + HVNCL, nullptr,
        simc, nullptr, nullptr, 1024, 1024, 1024, 2048,
        2, 4 * Mi, 0, 4 * Mi, 0, Mi, 0, 0);

    // 5) softmax blend -> split attn + asum
    softmax_combine<<<512, 256>>>(scc, scr, cls_score, Hp + HATH, Hp + HATL, asum);

    // 6) attn@v: M=512,N=128 per head, K=2048. z1=head (A shared across branch)
    hgemm<64, false, false, true><<<dim3(1, 8, 16), 256, SM64>>>(
        Hp + HATH, Hp + HATL, Hp + HVTCH, Hp + HVTCL, nullptr,
        nullptr, Hp + HXCCH, Hp + HXCCL, 2048, 2048, 2048, 2048,
        8, Mi, 0, 128LL * 2048, 4 * Mi, 128, 2 * Mi, 0);

    // 7) x_ori into concat cols [1024,2048), both branches
    copy_xori<<<dim3(512, 2), 256>>>(kvc, Hp + HXCCH, Hp + HXCCL);

    // 8) second-round masked weights
    mask_renorm<<<512, 256>>>(asum, simc, simr,
                              Hp + HS2H, Hp + HS2L, Hp + HOWH, Hp + HOWL);

    // 9) output linears -> out cols [1024,3072), z=branch
    hgemm<64, true, true, false><<<dim3(16, 8, 2), 256, SM64>>>(
        Hp + HXCCH, Hp + HXCCL, Hp + HWLCH, Hp + HWLCL, bias2,
        out + 1024, nullptr, nullptr, 2048, 2048, 2048, 3072,
        2, 2 * Mi, 0, 8 * Mi, 0, OSTR, 0, 2048);

    // 10) support features -> out cols [0,1024), z=branch
    hgemm<64, false, true, false><<<dim3(8, 8, 2), 256, SM64>>>(
        Hp + HS2H, Hp + HS2L, Hp + HVTCH, Hp + HVTCL, nullptr,
        out, nullptr, nullptr, 2048, 2048, 2048, 3072,
        2, 2 * Mi, 0, 4 * Mi, 0, OSTR, 0, 0);
}

// round 5
// speedup vs baseline: 4.6421x; 1.0240x over previous
#include <cuda_runtime.h>
#include <cuda_fp16.h>
#include <cstdint>

// ===========================================================================
// Fixed shapes: B=1, N1=512, N2=2048, C=1024, H=8, hd=128
// All GEMMs: mma.sync m16n8k16 fp16, 3-term hi/lo split (err ~2^-21).
// Round 5: cp.async (LDGSTS) double-buffered mainloop; batched elementwise.
// ===========================================================================

constexpr size_t Mi = 1024 * 1024;

// ------------------------- fp32 scratch layout ------------------------------
constexpr size_t F_QC   = 0;                 // [512,1024] x2 branches
constexpr size_t F_QR   = F_QC   + Mi / 2;
constexpr size_t F_KVC  = F_QR   + Mi / 2;   // [2048,2048] x2
constexpr size_t F_KVR  = F_KVC  + 4 * Mi;
constexpr size_t F_SCC  = F_KVR  + 4 * Mi;   // [8,512,2048] x2
constexpr size_t F_SCR  = F_SCC  + 8 * Mi;
constexpr size_t F_ASUM = F_SCR  + 8 * Mi;   // [512,2048]
constexpr size_t F_SIMC = F_ASUM + Mi;
constexpr size_t F_SIMR = F_SIMC + Mi;
constexpr size_t F_BIAS = F_SIMR + Mi;       // [2,2048]
constexpr size_t F_TOTAL = F_BIAS + 4096;
__device__ float g_scratch[F_TOTAL];

// ------------------------- fp16 plane layout --------------------------------
constexpr size_t HXCH  = 0;                  // x [2048,1024]
constexpr size_t HXCL  = HXCH  + 2 * Mi;
constexpr size_t HXRH  = HXCL  + 2 * Mi;
constexpr size_t HXRL  = HXRH  + 2 * Mi;
constexpr size_t HWQCH = HXRL  + 2 * Mi;     // WqT [1024,1024]
constexpr size_t HWQCL = HWQCH + 1 * Mi;
constexpr size_t HWQRH = HWQCL + 1 * Mi;
constexpr size_t HWQRL = HWQRH + 1 * Mi;
constexpr size_t HWKCH = HWQRL + 1 * Mi;     // WkvT [2048,1024]
constexpr size_t HWKCL = HWKCH + 2 * Mi;
constexpr size_t HWKRH = HWKCL + 2 * Mi;
constexpr size_t HWKRL = HWKRH + 2 * Mi;
constexpr size_t HWLCH = HWKRL + 2 * Mi;     // WlinT [2048,2048]
constexpr size_t HWLCL = HWLCH + 4 * Mi;
constexpr size_t HWLRH = HWLCL + 4 * Mi;
constexpr size_t HWLRL = HWLRH + 4 * Mi;
constexpr size_t HQCH  = HWLRL + 4 * Mi;     // q norm [512,1024]
constexpr size_t HQCL  = HQCH  + Mi / 2;
constexpr size_t HQRH  = HQCL  + Mi / 2;
constexpr size_t HQRL  = HQRH  + Mi / 2;
constexpr size_t HKCH  = HQRL  + Mi / 2;     // k norm [2048,1024]
constexpr size_t HKCL  = HKCH  + 2 * Mi;
constexpr size_t HKRH  = HKCL  + 2 * Mi;
constexpr size_t HKRL  = HKRH  + 2 * Mi;
constexpr size_t HVNCH = HKRL  + 2 * Mi;     // v norm [2048,1024]
constexpr size_t HVNCL = HVNCH + 2 * Mi;
constexpr size_t HVNRH = HVNCL + 2 * Mi;
constexpr size_t HVNRL = HVNRH + 2 * Mi;
constexpr size_t HVTCH = HVNRL + 2 * Mi;     // vT [1024,2048]
constexpr size_t HVTCL = HVTCH + 2 * Mi;
constexpr size_t HVTRH = HVTCL + 2 * Mi;
constexpr size_t HVTRL = HVTRH + 2 * Mi;
constexpr size_t HATH  = HVTRL + 2 * Mi;     // attn [8,512,2048]
constexpr size_t HATL  = HATH  + 8 * Mi;
constexpr size_t HS2H  = HATL  + 8 * Mi;     // s2 / ow [512,2048]
constexpr size_t HS2L  = HS2H  + Mi;
constexpr size_t HOWH  = HS2L  + Mi;
constexpr size_t HOWL  = HOWH  + Mi;
constexpr size_t HXCCH = HOWL  + Mi;         // concat [512,2048]
constexpr size_t HXCCL = HXCCH + Mi;
constexpr size_t HXCRH = HXCCL + Mi;
constexpr size_t HXCRL = HXCRH + Mi;
constexpr size_t H_TOTAL = HXCRL + Mi;
__device__ __half g_half[H_TOTAL];

// ----------------------------- helpers --------------------------------------
__device__ __forceinline__ uint32_t smem_u32(const void* p) {
    uint32_t a;
    asm("{ .reg .u64 t; cvta.to.shared.u64 t, %1; cvt.u32.u64 %0, t; }"
        : "=r"(a) : "l"(p));
    return a;
}
__device__ __forceinline__ uint32_t pack2(__half a, __half b) {
    __half2 h = __halves2half2(a, b);
    return *(uint32_t*)&h;
}
__device__ __forceinline__ void split1(float x, __half& h, __half& l) {
    h = __float2half_rn(x);
    l = __float2half_rn(x - __half2float(h));
}
__device__ __forceinline__ void split4(float4 v, uint2& hi, uint2& lo) {
    __half h0, h1, h2, h3, l0, l1, l2, l3;
    split1(v.x, h0, l0); split1(v.y, h1, l1);
    split1(v.z, h2, l2); split1(v.w, h3, l3);
    hi.x = pack2(h0, h1); hi.y = pack2(h2, h3);
    lo.x = pack2(l0, l1); lo.y = pack2(l2, l3);
}
__device__ __forceinline__ void ldsm4(uint32_t* r, uint32_t addr) {
    asm volatile("ldmatrix.sync.aligned.m8n8.x4.shared.b16 {%0,%1,%2,%3}, [%4];"
                 : "=r"(r[0]), "=r"(r[1]), "=r"(r[2]), "=r"(r[3]) : "r"(addr));
}
__device__ __forceinline__ void mma16816(float* d, const uint32_t* a, const uint32_t* b) {
    asm volatile("mma.sync.aligned.m16n8k16.row.col.f32.f16.f16.f32 "
                 "{%0,%1,%2,%3}, {%4,%5,%6,%7}, {%8,%9}, {%0,%1,%2,%3};"
                 : "+f"(d[0]), "+f"(d[1]), "+f"(d[2]), "+f"(d[3])
                 : "r"(a[0]), "r"(a[1]), "r"(a[2]), "r"(a[3]),
                   "r"(b[0]), "r"(b[1]));
}
__device__ __forceinline__ void cp16(uint32_t dst, const void* src) {
    asm volatile("cp.async.cg.shared.global [%0], [%1], 16;"
                 :: "r"(dst), "l"(src));
}
#define CP_COMMIT() asm volatile("cp.async.commit_group;" ::: "memory")
#define CP_WAIT1() asm volatile("cp.async.wait_group 1;" ::: "memory")
#define CP_WAIT0() asm volatile("cp.async.wait_group 0;" ::: "memory")

// ------------------------------- hgemm (NT) ----------------------------------
// C[M,N] = (Ah+Al)[M,K]*(Bh+Bl)[N,K]^T (3-term). CTA tile TMx128x32, 8 warps.
// cp.async double-buffered. blockIdx.z -> (z1 = z%z1n, z2 = z/z1n).
template <int TM, bool BIAS, bool FOUT, bool SPLITOUT>
__global__ void __launch_bounds__(256)
hgemm(const __half* __restrict__ Ah_g, const __half* __restrict__ Al_g,
      const __half* __restrict__ Bh_g, const __half* __restrict__ Bl_g,
      const float* __restrict__ bias,
      float* C, __half* Chi, __half* Clo,
      int K, int lda, int ldb, int ldc, int z1n,
      long long a_s1, long long a_s2, long long b_s1, long long b_s2,
      long long c_s1, long long c_s2, long long bias_s)
{
    constexpr int ASZ = TM * 80;            // bytes per A plane
    constexpr int STAGE = 2 * ASZ + 20480;  // + 2 B planes (128*80 each)
    constexpr int AJ = TM / 64;
    constexpr int WM = (TM == 128) ? 64 : 32;
    constexpr int MI = WM / 16;

    extern __shared__ char dsm[];
    const uint32_t sb = smem_u32(dsm);
    const int tid = threadIdx.x;

    const int z1 = blockIdx.z % z1n, z2 = blockIdx.z / z1n;
    const long long aoff = (long long)z1 * a_s1 + (long long)z2 * a_s2 +
                           (long long)blockIdx.y * TM * lda;
    const long long boff = (long long)z1 * b_s1 + (long long)z2 * b_s2 +
                           (long long)blockIdx.x * 128 * ldb;
    const long long coff = (long long)z1 * c_s1 + (long long)z2 * c_s2;
    Ah_g += aoff; Al_g += aoff;
    Bh_g += boff; Bl_g += boff;
    if (FOUT) C += coff;
    if (SPLITOUT) { Chi += coff; Clo += coff; }
    if (BIAS) bias += z1 * bias_s;

    const int lrow = tid >> 2;        // 0..63
    const int lc16 = tid & 3;         // 16B chunk within 64B k-row

    const int lane = tid & 31, w = tid >> 5;
    const int wm = (w >> 2) * WM;
    const int wn = (w & 3) << 5;
    const int g = lane >> 3, r = lane & 7;
    const int a_r  = r + ((g & 1) << 3);
    const int a_kb = (g >> 1) << 3;
    const int b_r  = r + ((g >> 1) << 3);
    const int b_kb = (g & 1) << 3;

    float acc[MI][4][4];
#pragma unroll
    for (int i = 0; i < MI; i++)
#pragma unroll
        for (int j = 0; j < 4; j++)
#pragma unroll
            for (int e = 0; e < 4; e++) acc[i][j][e] = 0.f;

    // async load of one k-tile into stage s
    auto LOADA = [&](int k0, int s) {
        const uint32_t base = sb + (uint32_t)s * STAGE;
#pragma unroll
        for (int j = 0; j < AJ; j++) {
            uint32_t so = (uint32_t)(lrow + j * 64) * 80 + lc16 * 16;
            size_t oa = (size_t)(lrow + j * 64) * lda + k0 + lc16 * 8;
            cp16(base + so, Ah_g + oa);
            cp16(base + ASZ + so, Al_g + oa);
        }
#pragma unroll
        for (int j = 0; j < 2; j++) {
            uint32_t so = (uint32_t)(lrow + j * 64) * 80 + lc16 * 16;
            size_t ob = (size_t)(lrow + j * 64) * ldb + k0 + lc16 * 8;
            cp16(base + 2 * ASZ + so, Bh_g + ob);
            cp16(base + 2 * ASZ + 10240 + so, Bl_g + ob);
        }
        CP_COMMIT();
    };

    auto COMPUTE = [&](int s) {
        const uint32_t base = sb + (uint32_t)s * STAGE;
#pragma unroll
        for (int ks = 0; ks < 32; ks += 16) {
            uint32_t ah[4 * MI], bh[8];
#pragma unroll
            for (int i = 0; i < MI; i++)
                ldsm4(&ah[4 * i], base + (uint32_t)(wm + i * 16 + a_r) * 80 +
                                  (uint32_t)(ks + a_kb) * 2);
            ldsm4(&bh[0], base + 2 * ASZ + (uint32_t)(wn + b_r) * 80 +
                          (uint32_t)(ks + b_kb) * 2);
            ldsm4(&bh[4], base + 2 * ASZ + (uint32_t)(wn + 16 + b_r) * 80 +
                          (uint32_t)(ks + b_kb) * 2);
#pragma unroll
            for (int i = 0; i < MI; i++)
#pragma unroll
                for (int j = 0; j < 4; j++)
                    mma16816(acc[i][j], &ah[4 * i], &bh[2 * j]);
            uint32_t bl[8];
            ldsm4(&bl[0], base + 2 * ASZ + 10240 + (uint32_t)(wn + b_r) * 80 +
                          (uint32_t)(ks + b_kb) * 2);
            ldsm4(&bl[4], base + 2 * ASZ + 10240 + (uint32_t)(wn + 16 + b_r) * 80 +
                          (uint32_t)(ks + b_kb) * 2);
#pragma unroll
            for (int i = 0; i < MI; i++)
#pragma unroll
                for (int j = 0; j < 4; j++)
                    mma16816(acc[i][j], &ah[4 * i], &bl[2 * j]);
            uint32_t al[4 * MI];
#pragma unroll
            for (int i = 0; i < MI; i++)
                ldsm4(&al[4 * i], base + ASZ + (uint32_t)(wm + i * 16 + a_r) * 80 +
                                  (uint32_t)(ks + a_kb) * 2);
#pragma unroll
            for (int i = 0; i < MI; i++)
#pragma unroll
                for (int j = 0; j < 4; j++)
                    mma16816(acc[i][j], &al[4 * i], &bh[2 * j]);
        }
    };

    const int T = K >> 5;
    LOADA(0, 0);
    for (int t = 0; t < T; t++) {
        if (t + 1 < T) {
            LOADA((t + 1) << 5, (t + 1) & 1);
            CP_WAIT1();
        } else {
            CP_WAIT0();
        }
        __syncthreads();
        COMPUTE(t & 1);
        __syncthreads();
    }

    // ------------------------------ epilogue ---------------------------------
    const int rbase = blockIdx.y * TM + wm;
    const int cbase = blockIdx.x * 128 + wn;
#pragma unroll
    for (int i = 0; i < MI; i++) {
#pragma unroll
        for (int j = 0; j < 4; j++) {
            int row0 = rbase + i * 16 + (lane >> 2);
            int col = cbase + j * 8 + ((lane & 3) << 1);
            float2 v0 = {acc[i][j][0], acc[i][j][1]};
            float2 v1 = {acc[i][j][2], acc[i][j][3]};
            if (BIAS) {
                float2 b2 = *(const float2*)(bias + col);
                v0.x += b2.x; v0.y += b2.y;
                v1.x += b2.x; v1.y += b2.y;
            }
            if (FOUT) {
                *(float2*)(C + (size_t)row0 * ldc + col) = v0;
                *(float2*)(C + (size_t)(row0 + 8) * ldc + col) = v1;
            }
            if (SPLITOUT) {
                __half h0, h1, l0, l1;
                split1(v0.x, h0, l0); split1(v0.y, h1, l1);
                *(uint32_t*)(Chi + (size_t)row0 * ldc + col) = pack2(h0, h1);
                *(uint32_t*)(Clo + (size_t)row0 * ldc + col) = pack2(l0, l1);
                split1(v1.x, h0, l0); split1(v1.y, h1, l1);
                *(uint32_t*)(Chi + (size_t)(row0 + 8) * ldc + col) = pack2(h0, h1);
                *(uint32_t*)(Clo + (size_t)(row0 + 8) * ldc + col) = pack2(l0, l1);
            }
        }
    }
}

// ----------------------- transpose + split to fp16 ---------------------------
__global__ void __launch_bounds__(256)
transpose_split(const float* __restrict__ in, __half* __restrict__ hi,
                __half* __restrict__ lo, int ldin, int ldout)
{
    __shared__ float t[32][33];
    const int bx = blockIdx.x * 32, by = blockIdx.y * 32;
    const int x = threadIdx.x, y = threadIdx.y;
#pragma unroll
    for (int j = 0; j < 32; j += 8)
        t[y + j][x] = in[(size_t)(by + y + j) * ldin + bx + x];
    __syncthreads();
#pragma unroll
    for (int j = 0; j < 32; j += 8) {
        float v = t[x][y + j];
        __half h, l;
        split1(v, h, l);
        size_t o = (size_t)(bx + y + j) * ldout + by + x;
        hi[o] = h;
        lo[o] = l;
    }
}

// --------------------------- plain split to fp16 -----------------------------
// grid.y = branch; in/out strides in float4 / uint2 units
__global__ void __launch_bounds__(256)
split_f16(const float* __restrict__ in, __half* __restrict__ hi,
          __half* __restrict__ lo, int n4, long long in_bs, long long out_bs)
{
    in += blockIdx.y * in_bs;
    hi += blockIdx.y * out_bs;
    lo += blockIdx.y * out_bs;
    int i = blockIdx.x * 256 + threadIdx.x;
    if (i >= n4) return;
    float4 v = ((const float4*)in)[i];
    uint2 h, l;
    split4(v, h, l);
    ((uint2*)hi)[i] = h;
    ((uint2*)lo)[i] = l;
}

// -------------------- L2 normalize (per head) + split -------------------------
// grid.y = branch
__global__ void __launch_bounds__(256)
l2norm_split(const float* __restrict__ src, __half* __restrict__ hi,
             __half* __restrict__ lo, int lds, int ldd, int nvec,
             long long src_bs, long long dst_bs)
{
    src += blockIdx.y * src_bs;
    hi += blockIdx.y * dst_bs;
    lo += blockIdx.y * dst_bs;
    int vec = blockIdx.x * 8 + (threadIdx.x >> 5);
    int lane = threadIdx.x & 31;
    if (vec >= nvec) return;
    int row = vec >> 3, h = vec & 7;
    const float* s = src + (size_t)row * lds + h * 128 + lane * 4;
    float4 v = *(const float4*)s;
    float ss = v.x * v.x + v.y * v.y + v.z * v.z + v.w * v.w;
#pragma unroll
    for (int o = 16; o; o >>= 1) ss += __shfl_xor_sync(0xffffffffu, ss, o);
    float inv = 1.0f / sqrtf(ss);
    float4 o4 = {v.x * inv, v.y * inv, v.z * inv, v.w * inv};
    uint2 hh, ll;
    split4(o4, hh, ll);
    size_t o = (size_t)row * ldd + h * 128 + lane * 4;
    *(uint2*)(hi + o) = hh;
    *(uint2*)(lo + o) = ll;
}

// ------------------------------ block reductions -----------------------------
static __device__ __forceinline__ float blockReduceMax(float v) {
    __shared__ float s[8];
#pragma unroll
    for (int o = 16; o; o >>= 1) v = fmaxf(v, __shfl_xor_sync(0xffffffffu, v, o));
    if ((threadIdx.x & 31) == 0) s[threadIdx.x >> 5] = v;
    __syncthreads();
    v = s[threadIdx.x & 7];
#pragma unroll
    for (int o = 4; o; o >>= 1) v = fmaxf(v, __shfl_xor_sync(0xffffffffu, v, o));
    __syncthreads();
    return v;
}
static __device__ __forceinline__ float blockReduceSum(float v) {
    __shared__ float s[8];
#pragma unroll
    for (int o = 16; o; o >>= 1) v += __shfl_xor_sync(0xffffffffu, v, o);
    if ((threadIdx.x & 31) == 0) s[threadIdx.x >> 5] = v;
    __syncthreads();
    v = s[threadIdx.x & 7];
#pragma unroll
    for (int o = 4; o; o >>= 1) v += __shfl_xor_sync(0xffffffffu, v, o);
    __syncthreads();
    return v;
}

// --------------------- softmax blend, write split attn -----------------------
__global__ void __launch_bounds__(256)
softmax_combine(const float* __restrict__ sc_cls, const float* __restrict__ sc_reg,
                const float* __restrict__ cls_score,
                __half* __restrict__ attn_h, __half* __restrict__ attn_l,
                float* __restrict__ asum)
{
    const int q = blockIdx.x;
    const int tid = threadIdx.x;
    float cs[8], accum[8];
#pragma unroll
    for (int j = 0; j < 8; j++) {
        cs[j] = cls_score[j * 256 + tid];
        accum[j] = 0.f;
    }
    for (int h = 0; h < 8; h++) {
        const float* pc = sc_cls + ((size_t)h * 512 + q) * 2048;
        const float* pr = sc_reg + ((size_t)h * 512 + q) * 2048;
        float c[8], r[8];
        float mc = -1e30f, mr = -1e30f;
#pragma unroll
        for (int j = 0; j < 8; j++) {
            int k = j * 256 + tid;
            c[j] = pc[k] * 25.0f * cs[j];
            r[j] = pr[k] * 25.0f;
            mc = fmaxf(mc, c[j]);
            mr = fmaxf(mr, r[j]);
        }
        mc = blockReduceMax(mc);
        mr = blockReduceMax(mr);
        float sc = 0.f, sr = 0.f;
#pragma unroll
        for (int j = 0; j < 8; j++) {
            c[j] = expf(c[j] - mc);
            r[j] = expf(r[j] - mr);
            sc += c[j];
            sr += r[j];
        }
        sc = blockReduceSum(sc);
        sr = blockReduceSum(sr);
        float ic = 0.5f / sc, ir = 0.5f / sr;
        size_t pb = ((size_t)h * 512 + q) * 2048;
#pragma unroll
        for (int j = 0; j < 8; j++) {
            float a = c[j] * ic + r[j] * ir;
            __half hh, ll;
            split1(a, hh, ll);
            attn_h[pb + j * 256 + tid] = hh;
            attn_l[pb + j * 256 + tid] = ll;
            accum[j] += a;
        }
    }
#pragma unroll
    for (int j = 0; j < 8; j++) asum[(size_t)q * 2048 + j * 256 + tid] = accum[j];
}

// ------------- masked renormalized second-round weights (split) --------------
__global__ void __launch_bounds__(256)
mask_renorm(const float* __restrict__ asum, const float* __restrict__ simc,
            const float* __restrict__ simr,
            __half* __restrict__ s2h, __half* __restrict__ s2l,
            __half* __restrict__ owh, __half* __restrict__ owl)
{
    const int q = blockIdx.x;
    const int tid = threadIdx.x;
    float a[8];
    float mx = -1e30f;
#pragma unroll
    for (int j = 0; j < 8; j++) {
        a[j] = asum[(size_t)q * 2048 + j * 256 + tid] * 0.125f;
        mx = fmaxf(mx, a[j]);
    }
    mx = blockReduceMax(mx);
    float sum = 0.f;
#pragma unroll
    for (int j = 0; j < 8; j++) {
        a[j] = expf(a[j] - mx);
        sum += a[j];
    }
    sum = blockReduceSum(sum);
    float inv = 1.0f / sum;
    float sm = 0.f;
#pragma unroll
    for (int j = 0; j < 8; j++) {
        int k = j * 256 + tid;
        float m = (simc[(size_t)q * 2048 + k] * 0.125f > 0.75f) ? 1.0f : 0.0f;
        a[j] = a[j] * inv * m;
        sm += a[j];
    }
    sm = blockReduceSum(sm);
    inv = 1.0f / sm;
    float so = 0.f;
    float o[8];
#pragma unroll
    for (int j = 0; j < 8; j++) {
        int k = j * 256 + tid;
        a[j] *= inv;
        __half hh, ll;
        split1(a[j], hh, ll);
        s2h[(size_t)q * 2048 + k] = hh;
        s2l[(size_t)q * 2048 + k] = ll;
        float m = (simr[(size_t)q * 2048 + k] * 0.125f > 0.99f) ? 1.0f : 0.0f;
        o[j] = a[j] * m;
        so += o[j];
    }
    so = blockReduceSum(so);
    inv = 1.0f / so;
#pragma unroll
    for (int j = 0; j < 8; j++) {
        float v = o[j] * inv;
        __half hh, ll;
        split1(v, hh, ll);
        owh[(size_t)q * 2048 + j * 256 + tid] = hh;
        owl[(size_t)q * 2048 + j * 256 + tid] = ll;
    }
}

// -------------------- copy x_ori into concat (split) -------------------------
__global__ void __launch_bounds__(256)
copy_xori(const float* __restrict__ kv, __half* __restrict__ xh,
          __half* __restrict__ xl)
{
    int z = blockIdx.y;
    kv += (size_t)z * 4 * Mi;
    xh += (size_t)z * 2 * Mi;
    xl += (size_t)z * 2 * Mi;
    int idx = blockIdx.x * 256 + threadIdx.x;
    int q = idx >> 8;
    int c4 = idx & 255;
    size_t off = (size_t)q * 2048 + 1024 + (size_t)c4 * 4;
    float4 v = *(const float4*)(kv + off);
    uint2 h, l;
    split4(v, h, l);
    *(uint2*)(xh + off) = h;
    *(uint2*)(xl + off) = l;
}

// ------------------------------ bias copy ------------------------------------
__global__ void copy_bias(const float* __restrict__ b0, const float* __restrict__ b1,
                          float* __restrict__ dst)
{
    int i = blockIdx.x * 256 + threadIdx.x;
    if (i < 2048) { dst[i] = b0[i]; dst[2048 + i] = b1[i]; }
}

// --------------------------------- launch ------------------------------------
extern "C" void kernel_launch(void* const* d_in, const int* in_sizes, int n_in,
                              void* d_out, int out_size)
{
    const float* x_cls     = (const float*)d_in[0];
    const float* cls_score = (const float*)d_in[2];
    const float* W_q_cls   = (const float*)d_in[4];
    const float* W_kv_cls  = (const float*)d_in[5];
    const float* W_q_reg   = (const float*)d_in[6];
    const float* W_kv_reg  = (const float*)d_in[7];
    const float* W_lin     = (const float*)d_in[8];
    const float* b_lin     = (const float*)d_in[9];
    const float* W_lin_reg = (const float*)d_in[10];
    const float* b_lin_reg = (const float*)d_in[11];
    float* out = (float*)d_out;

    float* F = nullptr;
    __half* Hp = nullptr;
    cudaGetSymbolAddress((void**)&F, g_scratch);
    cudaGetSymbolAddress((void**)&Hp, g_half);

    float* qc   = F + F_QC;
    float* kvc  = F + F_KVC;
    float* scc  = F + F_SCC;
    float* scr  = F + F_SCR;
    float* asum = F + F_ASUM;
    float* simc = F + F_SIMC;
    float* simr = F + F_SIMR;
    float* bias2 = F + F_BIAS;

    constexpr int SM128 = 2 * (2 * 128 * 80 + 20480);  // 81920
    constexpr int SM64  = 2 * (2 * 64 * 80 + 20480);   // 61440
    cudaFuncSetAttribute(hgemm<128, false, true, false>,
                         cudaFuncAttributeMaxDynamicSharedMemorySize, SM128);
    cudaFuncSetAttribute(hgemm<64, false, true, false>,
                         cudaFuncAttributeMaxDynamicSharedMemorySize, SM64);
    cudaFuncSetAttribute(hgemm<64, true, true, false>,
                         cudaFuncAttributeMaxDynamicSharedMemorySize, SM64);
    cudaFuncSetAttribute(hgemm<64, false, false, true>,
                         cudaFuncAttributeMaxDynamicSharedMemorySize, SM64);

    dim3 tb(32, 8);
    const long long OSTR = 512LL * 3072;   // out branch stride

    // 0) transpose+split weights; split x (both branches, d_in[0]/[1] adjacent
    //    is NOT guaranteed -> separate launches for x); copy biases
    transpose_split<<<dim3(32, 32), tb>>>(W_q_cls, Hp + HWQCH, Hp + HWQCL, 1024, 1024);
    transpose_split<<<dim3(32, 32), tb>>>(W_q_reg, Hp + HWQRH, Hp + HWQRL, 1024, 1024);
    transpose_split<<<dim3(64, 32), tb>>>(W_kv_cls, Hp + HWKCH, Hp + HWKCL, 2048, 1024);
    transpose_split<<<dim3(64, 32), tb>>>(W_kv_reg, Hp + HWKRH, Hp + HWKRL, 2048, 1024);
    transpose_split<<<dim3(64, 64), tb>>>(W_lin, Hp + HWLCH, Hp + HWLCL, 2048, 2048);
    transpose_split<<<dim3(64, 64), tb>>>(W_lin_reg, Hp + HWLRH, Hp + HWLRL, 2048, 2048);
    split_f16<<<dim3(2048, 1), 256>>>(x_cls, Hp + HXCH, Hp + HXCL, 2048 * 256, 0, 0);
    split_f16<<<dim3(2048, 1), 256>>>((const float*)d_in[1], Hp + HXRH, Hp + HXRL,
                                      2048 * 256, 0, 0);
    copy_bias<<<8, 256>>>(b_lin, b_lin_reg, bias2);

    // 1) q projections, both branches (z=branch): M=512,N=1024,K=1024
    hgemm<64, false, true, false><<<dim3(8, 8, 2), 256, SM64>>>(
        Hp + HXCH, Hp + HXCL, Hp + HWQCH, Hp + HWQCL, nullptr,
        qc, nullptr, nullptr, 1024, 1024, 1024, 1024,
        2, 4 * Mi, 0, 2 * Mi, 0, Mi / 2, 0, 0);
    // kv projections: M=2048,N=2048,K=1024
    hgemm<128, false, true, false><<<dim3(16, 16, 2), 256, SM128>>>(
        Hp + HXCH, Hp + HXCL, Hp + HWKCH, Hp + HWKCL, nullptr,
        kvc, nullptr, nullptr, 1024, 1024, 1024, 2048,
        2, 4 * Mi, 0, 4 * Mi, 0, 4 * Mi, 0, 0);

    // 2) L2 norms + split (branch batched); transpose+split raw v
    l2norm_split<<<dim3(512, 2), 256>>>(qc, Hp + HQCH, Hp + HQCL,
                                        1024, 1024, 512 * 8, Mi / 2, Mi);
    l2norm_split<<<dim3(2048, 2), 256>>>(kvc, Hp + HKCH, Hp + HKCL,
                                         2048, 1024, 2048 * 8, 4 * Mi, 4 * Mi);
    l2norm_split<<<dim3(2048, 2), 256>>>(kvc + 1024, Hp + HVNCH, Hp + HVNCL,
                                         2048, 1024, 2048 * 8, 4 * Mi, 4 * Mi);
    transpose_split<<<dim3(32, 64), tb>>>(kvc + 1024, Hp + HVTCH, Hp + HVTCL, 2048, 2048);
    transpose_split<<<dim3(32, 64), tb>>>(kvc + 4 * Mi + 1024, Hp + HVTRH, Hp + HVTRL,
                                          2048, 2048);

    // 3) scores: z = branch*8 + head (z1=head, z2=branch). M=512,N=2048,K=128
    hgemm<64, false, true, false><<<dim3(16, 8, 16), 256, SM64>>>(
        Hp + HQCH, Hp + HQCL, Hp + HKCH, Hp + HKCL, nullptr,
        scc, nullptr, nullptr, 128, 1024, 1024, 2048,
        8, 128, Mi, 128, 4 * Mi, Mi, 8 * Mi, 0);

    // 4) v-sims: M=512,N=2048,K=1024, z=branch
    hgemm<64, false, true, false><<<dim3(16, 8, 2), 256, SM64>>>(
        Hp + HVNCH, Hp + HVNCL, Hp + HVNCH, Hp + HVNCL, nullptr,
        simc, nullptr, nullptr, 1024, 1024, 1024, 2048,
        2, 4 * Mi, 0, 4 * Mi, 0, Mi, 0, 0);

    // 5) softmax blend -> split attn + asum
    softmax_combine<<<512, 256>>>(scc, scr, cls_score, Hp + HATH, Hp + HATL, asum);

    // 6) attn@v: M=512,N=128 per head, K=2048. z1=head (A shared across branch)
    hgemm<64, false, false, true><<<dim3(1, 8, 16), 256, SM64>>>(
        Hp + HATH, Hp + HATL, Hp + HVTCH, Hp + HVTCL, nullptr,
        nullptr, Hp + HXCCH, Hp + HXCCL, 2048, 2048, 2048, 2048,
        8, Mi, 0, 128LL * 2048, 4 * Mi, 128, 2 * Mi, 0);

    // 7) x_ori into concat cols [1024,2048), both branches
    copy_xori<<<dim3(512, 2), 256>>>(kvc, Hp + HXCCH, Hp + HXCCL);

    // 8) second-round masked weights
    mask_renorm<<<512, 256>>>(asum, simc, simr,
                              Hp + HS2H, Hp + HS2L, Hp + HOWH, Hp + HOWL);

    // 9) output linears -> out cols [1024,3072), z=branch
    hgemm<64, true, true, false><<<dim3(16, 8, 2), 256, SM64>>>(
        Hp + HXCCH, Hp + HXCCL, Hp + HWLCH, Hp + HWLCL, bias2,
        out + 1024, nullptr, nullptr, 2048, 2048, 2048, 3072,
        2, 2 * Mi, 0, 8 * Mi, 0, OSTR, 0, 2048);

    // 10) support features -> out cols [0,1024), z=branch
    hgemm<64, false, true, false><<<dim3(8, 8, 2), 256, SM64>>>(
        Hp + HS2H, Hp + HS2L, Hp + HVTCH, Hp + HVTCL, nullptr,
        out, nullptr, nullptr, 2048, 2048, 2048, 3072,
        2, 2 * Mi, 0, 4 * Mi, 0, OSTR, 0, 0);
}

// round 6
// speedup vs baseline: 4.7201x; 1.0168x over previous
#include <cuda_runtime.h>
#include <cuda_fp16.h>
#include <cstdint>

// ===========================================================================
// Fixed shapes: B=1, N1=512, N2=2048, C=1024, H=8, hd=128
// All GEMMs: mma.sync m16n8k16 fp16, 3-term hi/lo split (err ~2^-21).
// Round 6: 4-warp CTAs with 64x64 warp tiles -> smem traffic/area -45%.
// ===========================================================================

constexpr size_t Mi = 1024 * 1024;

// ------------------------- fp32 scratch layout ------------------------------
constexpr size_t F_QC   = 0;                 // [512,1024] x2 branches
constexpr size_t F_QR   = F_QC   + Mi / 2;
constexpr size_t F_KVC  = F_QR   + Mi / 2;   // [2048,2048] x2
constexpr size_t F_KVR  = F_KVC  + 4 * Mi;
constexpr size_t F_SCC  = F_KVR  + 4 * Mi;   // [8,512,2048] x2
constexpr size_t F_SCR  = F_SCC  + 8 * Mi;
constexpr size_t F_ASUM = F_SCR  + 8 * Mi;   // [512,2048]
constexpr size_t F_SIMC = F_ASUM + Mi;
constexpr size_t F_SIMR = F_SIMC + Mi;
constexpr size_t F_BIAS = F_SIMR + Mi;       // [2,2048]
constexpr size_t F_TOTAL = F_BIAS + 4096;
__device__ float g_scratch[F_TOTAL];

// ------------------------- fp16 plane layout --------------------------------
constexpr size_t HXCH  = 0;                  // x [2048,1024]
constexpr size_t HXCL  = HXCH  + 2 * Mi;
constexpr size_t HXRH  = HXCL  + 2 * Mi;
constexpr size_t HXRL  = HXRH  + 2 * Mi;
constexpr size_t HWQCH = HXRL  + 2 * Mi;     // WqT [1024,1024]
constexpr size_t HWQCL = HWQCH + 1 * Mi;
constexpr size_t HWQRH = HWQCL + 1 * Mi;
constexpr size_t HWQRL = HWQRH + 1 * Mi;
constexpr size_t HWKCH = HWQRL + 1 * Mi;     // WkvT [2048,1024]
constexpr size_t HWKCL = HWKCH + 2 * Mi;
constexpr size_t HWKRH = HWKCL + 2 * Mi;
constexpr size_t HWKRL = HWKRH + 2 * Mi;
constexpr size_t HWLCH = HWKRL + 2 * Mi;     // WlinT [2048,2048]
constexpr size_t HWLCL = HWLCH + 4 * Mi;
constexpr size_t HWLRH = HWLCL + 4 * Mi;
constexpr size_t HWLRL = HWLRH + 4 * Mi;
constexpr size_t HQCH  = HWLRL + 4 * Mi;     // q norm [512,1024]
constexpr size_t HQCL  = HQCH  + Mi / 2;
constexpr size_t HQRH  = HQCL  + Mi / 2;
constexpr size_t HQRL  = HQRH  + Mi / 2;
constexpr size_t HKCH  = HQRL  + Mi / 2;     // k norm [2048,1024]
constexpr size_t HKCL  = HKCH  + 2 * Mi;
constexpr size_t HKRH  = HKCL  + 2 * Mi;
constexpr size_t HKRL  = HKRH  + 2 * Mi;
constexpr size_t HVNCH = HKRL  + 2 * Mi;     // v norm [2048,1024]
constexpr size_t HVNCL = HVNCH + 2 * Mi;
constexpr size_t HVNRH = HVNCL + 2 * Mi;
constexpr size_t HVNRL = HVNRH + 2 * Mi;
constexpr size_t HVTCH = HVNRL + 2 * Mi;     // vT [1024,2048]
constexpr size_t HVTCL = HVTCH + 2 * Mi;
constexpr size_t HVTRH = HVTCL + 2 * Mi;
constexpr size_t HVTRL = HVTRH + 2 * Mi;
constexpr size_t HATH  = HVTRL + 2 * Mi;     // attn [8,512,2048]
constexpr size_t HATL  = HATH  + 8 * Mi;
constexpr size_t HS2H  = HATL  + 8 * Mi;     // s2 / ow [512,2048]
constexpr size_t HS2L  = HS2H  + Mi;
constexpr size_t HOWH  = HS2L  + Mi;
constexpr size_t HOWL  = HOWH  + Mi;
constexpr size_t HXCCH = HOWL  + Mi;         // concat [512,2048]
constexpr size_t HXCCL = HXCCH + Mi;
constexpr size_t HXCRH = HXCCL + Mi;
constexpr size_t HXCRL = HXCRH + Mi;
constexpr size_t H_TOTAL = HXCRL + Mi;
__device__ __half g_half[H_TOTAL];

// ----------------------------- helpers --------------------------------------
__device__ __forceinline__ uint32_t smem_u32(const void* p) {
    uint32_t a;
    asm("{ .reg .u64 t; cvta.to.shared.u64 t, %1; cvt.u32.u64 %0, t; }"
        : "=r"(a) : "l"(p));
    return a;
}
__device__ __forceinline__ uint32_t pack2(__half a, __half b) {
    __half2 h = __halves2half2(a, b);
    return *(uint32_t*)&h;
}
__device__ __forceinline__ void split1(float x, __half& h, __half& l) {
    h = __float2half_rn(x);
    l = __float2half_rn(x - __half2float(h));
}
__device__ __forceinline__ void split4(float4 v, uint2& hi, uint2& lo) {
    __half h0, h1, h2, h3, l0, l1, l2, l3;
    split1(v.x, h0, l0); split1(v.y, h1, l1);
    split1(v.z, h2, l2); split1(v.w, h3, l3);
    hi.x = pack2(h0, h1); hi.y = pack2(h2, h3);
    lo.x = pack2(l0, l1); lo.y = pack2(l2, l3);
}
__device__ __forceinline__ void ldsm4(uint32_t* r, uint32_t addr) {
    asm volatile("ldmatrix.sync.aligned.m8n8.x4.shared.b16 {%0,%1,%2,%3}, [%4];"
                 : "=r"(r[0]), "=r"(r[1]), "=r"(r[2]), "=r"(r[3]) : "r"(addr));
}
__device__ __forceinline__ void mma16816(float* d, const uint32_t* a, const uint32_t* b) {
    asm volatile("mma.sync.aligned.m16n8k16.row.col.f32.f16.f16.f32 "
                 "{%0,%1,%2,%3}, {%4,%5,%6,%7}, {%8,%9}, {%0,%1,%2,%3};"
                 : "+f"(d[0]), "+f"(d[1]), "+f"(d[2]), "+f"(d[3])
                 : "r"(a[0]), "r"(a[1]), "r"(a[2]), "r"(a[3]),
                   "r"(b[0]), "r"(b[1]));
}
__device__ __forceinline__ void cp16(uint32_t dst, const void* src) {
    asm volatile("cp.async.cg.shared.global [%0], [%1], 16;"
                 :: "r"(dst), "l"(src));
}
#define CP_COMMIT() asm volatile("cp.async.commit_group;" ::: "memory")
#define CP_WAIT1() asm volatile("cp.async.wait_group 1;" ::: "memory")
#define CP_WAIT0() asm volatile("cp.async.wait_group 0;" ::: "memory")

// ------------------------------- hgemm (NT) ----------------------------------
// C[M,N] = (Ah+Al)[M,K]*(Bh+Bl)[N,K]^T (3-term). CTA tile TMxTNx32, 4 warps
// arranged (TM/WM)x(TN/WN) = 2x2. cp.async double-buffered.
// blockIdx.z -> (z1 = z%z1n, z2 = z/z1n).
template <int TM, int TN, int WM, int WN, bool BIAS, bool FOUT, bool SPLITOUT>
__global__ void __launch_bounds__(128)
hgemm(const __half* __restrict__ Ah_g, const __half* __restrict__ Al_g,
      const __half* __restrict__ Bh_g, const __half* __restrict__ Bl_g,
      const float* __restrict__ bias,
      float* C, __half* Chi, __half* Clo,
      int K, int lda, int ldb, int ldc, int z1n,
      long long a_s1, long long a_s2, long long b_s1, long long b_s2,
      long long c_s1, long long c_s2, long long bias_s)
{
    constexpr int ASZ = TM * 80;            // bytes per A plane
    constexpr int BSZ = TN * 80;            // bytes per B plane
    constexpr int STAGE = 2 * ASZ + 2 * BSZ;
    constexpr int MI = WM / 16;             // A 16-row blocks per warp
    constexpr int NB = WN / 16;             // B 16-row ldsm blocks per warp
    constexpr int NJ = WN / 8;              // n8 mma blocks per warp
    constexpr int NGRP = TN / WN;           // warp columns (=2)

    extern __shared__ char dsm[];
    const uint32_t sb = smem_u32(dsm);
    const int tid = threadIdx.x;

    const int z1 = blockIdx.z % z1n, z2 = blockIdx.z / z1n;
    const long long aoff = (long long)z1 * a_s1 + (long long)z2 * a_s2 +
                           (long long)blockIdx.y * TM * lda;
    const long long boff = (long long)z1 * b_s1 + (long long)z2 * b_s2 +
                           (long long)blockIdx.x * TN * ldb;
    const long long coff = (long long)z1 * c_s1 + (long long)z2 * c_s2;
    Ah_g += aoff; Al_g += aoff;
    Bh_g += boff; Bl_g += boff;
    if (FOUT) C += coff;
    if (SPLITOUT) { Chi += coff; Clo += coff; }
    if (BIAS) bias += z1 * bias_s;

    const int lrow = tid >> 2;        // 0..31
    const int lc16 = tid & 3;         // 16B chunk within 64B k-row

    const int lane = tid & 31, w = tid >> 5;
    const int wm = (w / NGRP) * WM;
    const int wn = (w % NGRP) * WN;
    const int g = lane >> 3, r = lane & 7;
    const int a_r  = r + ((g & 1) << 3);
    const int a_kb = (g >> 1) << 3;
    const int b_r  = r + ((g >> 1) << 3);
    const int b_kb = (g & 1) << 3;

    float acc[MI][NJ][4];
#pragma unroll
    for (int i = 0; i < MI; i++)
#pragma unroll
        for (int j = 0; j < NJ; j++)
#pragma unroll
            for (int e = 0; e < 4; e++) acc[i][j][e] = 0.f;

    // async load of one k-tile into stage s
    auto LOADA = [&](int k0, int s) {
        const uint32_t base = sb + (uint32_t)s * STAGE;
#pragma unroll
        for (int j = 0; j < TM / 32; j++) {
            int row = lrow + j * 32;
            uint32_t so = (uint32_t)row * 80 + lc16 * 16;
            size_t oa = (size_t)row * lda + k0 + lc16 * 8;
            cp16(base + so, Ah_g + oa);
            cp16(base + ASZ + so, Al_g + oa);
        }
#pragma unroll
        for (int j = 0; j < TN / 32; j++) {
            int row = lrow + j * 32;
            uint32_t so = (uint32_t)row * 80 + lc16 * 16;
            size_t ob = (size_t)row * ldb + k0 + lc16 * 8;
            cp16(base + 2 * ASZ + so, Bh_g + ob);
            cp16(base + 2 * ASZ + BSZ + so, Bl_g + ob);
        }
        CP_COMMIT();
    };

    auto COMPUTE = [&](int s) {
        const uint32_t base = sb + (uint32_t)s * STAGE;
#pragma unroll
        for (int ks = 0; ks < 32; ks += 16) {
            uint32_t ah[4 * MI], bh[4 * NB];
#pragma unroll
            for (int i = 0; i < MI; i++)
                ldsm4(&ah[4 * i], base + (uint32_t)(wm + i * 16 + a_r) * 80 +
                                  (uint32_t)(ks + a_kb) * 2);
#pragma unroll
            for (int t = 0; t < NB; t++)
                ldsm4(&bh[4 * t], base + 2 * ASZ + (uint32_t)(wn + t * 16 + b_r) * 80 +
                                  (uint32_t)(ks + b_kb) * 2);
#pragma unroll
            for (int i = 0; i < MI; i++)
#pragma unroll
                for (int j = 0; j < NJ; j++)
                    mma16816(acc[i][j], &ah[4 * i], &bh[2 * j]);
            uint32_t bl[4 * NB];
#pragma unroll
            for (int t = 0; t < NB; t++)
                ldsm4(&bl[4 * t], base + 2 * ASZ + BSZ +
                                  (uint32_t)(wn + t * 16 + b_r) * 80 +
                                  (uint32_t)(ks + b_kb) * 2);
#pragma unroll
            for (int i = 0; i < MI; i++)
#pragma unroll
                for (int j = 0; j < NJ; j++)
                    mma16816(acc[i][j], &ah[4 * i], &bl[2 * j]);
            uint32_t al[4 * MI];
#pragma unroll
            for (int i = 0; i < MI; i++)
                ldsm4(&al[4 * i], base + ASZ + (uint32_t)(wm + i * 16 + a_r) * 80 +
                                  (uint32_t)(ks + a_kb) * 2);
#pragma unroll
            for (int i = 0; i < MI; i++)
#pragma unroll
                for (int j = 0; j < NJ; j++)
                    mma16816(acc[i][j], &al[4 * i], &bh[2 * j]);
        }
    };

    const int T = K >> 5;
    LOADA(0, 0);
    for (int t = 0; t < T; t++) {
        if (t + 1 < T) {
            LOADA((t + 1) << 5, (t + 1) & 1);
            CP_WAIT1();
        } else {
            CP_WAIT0();
        }
        __syncthreads();
        COMPUTE(t & 1);
        __syncthreads();
    }

    // ------------------------------ epilogue ---------------------------------
    const int rbase = blockIdx.y * TM + wm;
    const int cbase = blockIdx.x * TN + wn;
#pragma unroll
    for (int i = 0; i < MI; i++) {
#pragma unroll
        for (int j = 0; j < NJ; j++) {
            int row0 = rbase + i * 16 + (lane >> 2);
            int col = cbase + j * 8 + ((lane & 3) << 1);
            float2 v0 = {acc[i][j][0], acc[i][j][1]};
            float2 v1 = {acc[i][j][2], acc[i][j][3]};
            if (BIAS) {
                float2 b2 = *(const float2*)(bias + col);
                v0.x += b2.x; v0.y += b2.y;
                v1.x += b2.x; v1.y += b2.y;
            }
            if (FOUT) {
                *(float2*)(C + (size_t)row0 * ldc + col) = v0;
                *(float2*)(C + (size_t)(row0 + 8) * ldc + col) = v1;
            }
            if (SPLITOUT) {
                __half h0, h1, l0, l1;
                split1(v0.x, h0, l0); split1(v0.y, h1, l1);
                *(uint32_t*)(Chi + (size_t)row0 * ldc + col) = pack2(h0, h1);
                *(uint32_t*)(Clo + (size_t)row0 * ldc + col) = pack2(l0, l1);
                split1(v1.x, h0, l0); split1(v1.y, h1, l1);
                *(uint32_t*)(Chi + (size_t)(row0 + 8) * ldc + col) = pack2(h0, h1);
                *(uint32_t*)(Clo + (size_t)(row0 + 8) * ldc + col) = pack2(l0, l1);
            }
        }
    }
}

// ----------------------- transpose + split to fp16 ---------------------------
__global__ void __launch_bounds__(256)
transpose_split(const float* __restrict__ in, __half* __restrict__ hi,
                __half* __restrict__ lo, int ldin, int ldout)
{
    __shared__ float t[32][33];
    const int bx = blockIdx.x * 32, by = blockIdx.y * 32;
    const int x = threadIdx.x, y = threadIdx.y;
#pragma unroll
    for (int j = 0; j < 32; j += 8)
        t[y + j][x] = in[(size_t)(by + y + j) * ldin + bx + x];
    __syncthreads();
#pragma unroll
    for (int j = 0; j < 32; j += 8) {
        float v = t[x][y + j];
        __half h, l;
        split1(v, h, l);
        size_t o = (size_t)(bx + y + j) * ldout + by + x;
        hi[o] = h;
        lo[o] = l;
    }
}

// --------------------------- plain split to fp16 -----------------------------
__global__ void __launch_bounds__(256)
split_f16(const float* __restrict__ in, __half* __restrict__ hi,
          __half* __restrict__ lo, int n4)
{
    int i = blockIdx.x * 256 + threadIdx.x;
    if (i >= n4) return;
    float4 v = ((const float4*)in)[i];
    uint2 h, l;
    split4(v, h, l);
    ((uint2*)hi)[i] = h;
    ((uint2*)lo)[i] = l;
}

// -------------------- L2 normalize (per head) + split -------------------------
__global__ void __launch_bounds__(256)
l2norm_split(const float* __restrict__ src, __half* __restrict__ hi,
             __half* __restrict__ lo, int lds, int ldd, int nvec,
             long long src_bs, long long dst_bs)
{
    src += blockIdx.y * src_bs;
    hi += blockIdx.y * dst_bs;
    lo += blockIdx.y * dst_bs;
    int vec = blockIdx.x * 8 + (threadIdx.x >> 5);
    int lane = threadIdx.x & 31;
    if (vec >= nvec) return;
    int row = vec >> 3, h = vec & 7;
    const float* s = src + (size_t)row * lds + h * 128 + lane * 4;
    float4 v = *(const float4*)s;
    float ss = v.x * v.x + v.y * v.y + v.z * v.z + v.w * v.w;
#pragma unroll
    for (int o = 16; o; o >>= 1) ss += __shfl_xor_sync(0xffffffffu, ss, o);
    float inv = 1.0f / sqrtf(ss);
    float4 o4 = {v.x * inv, v.y * inv, v.z * inv, v.w * inv};
    uint2 hh, ll;
    split4(o4, hh, ll);
    size_t o = (size_t)row * ldd + h * 128 + lane * 4;
    *(uint2*)(hi + o) = hh;
    *(uint2*)(lo + o) = ll;
}

// ------------------------------ block reductions -----------------------------
static __device__ __forceinline__ float blockReduceMax(float v) {
    __shared__ float s[8];
#pragma unroll
    for (int o = 16; o; o >>= 1) v = fmaxf(v, __shfl_xor_sync(0xffffffffu, v, o));
    if ((threadIdx.x & 31) == 0) s[threadIdx.x >> 5] = v;
    __syncthreads();
    v = s[threadIdx.x & 7];
#pragma unroll
    for (int o = 4; o; o >>= 1) v = fmaxf(v, __shfl_xor_sync(0xffffffffu, v, o));
    __syncthreads();
    return v;
}
static __device__ __forceinline__ float blockReduceSum(float v) {
    __shared__ float s[8];
#pragma unroll
    for (int o = 16; o; o >>= 1) v += __shfl_xor_sync(0xffffffffu, v, o);
    if ((threadIdx.x & 31) == 0) s[threadIdx.x >> 5] = v;
    __syncthreads();
    v = s[threadIdx.x & 7];
#pragma unroll
    for (int o = 4; o; o >>= 1) v += __shfl_xor_sync(0xffffffffu, v, o);
    __syncthreads();
    return v;
}

// --------------------- softmax blend, write split attn -----------------------
__global__ void __launch_bounds__(256)
softmax_combine(const float* __restrict__ sc_cls, const float* __restrict__ sc_reg,
                const float* __restrict__ cls_score,
                __half* __restrict__ attn_h, __half* __restrict__ attn_l,
                float* __restrict__ asum)
{
    const int q = blockIdx.x;
    const int tid = threadIdx.x;
    float cs[8], accum[8];
#pragma unroll
    for (int j = 0; j < 8; j++) {
        cs[j] = cls_score[j * 256 + tid];
        accum[j] = 0.f;
    }
    for (int h = 0; h < 8; h++) {
        const float* pc = sc_cls + ((size_t)h * 512 + q) * 2048;
        const float* pr = sc_reg + ((size_t)h * 512 + q) * 2048;
        float c[8], r[8];
        float mc = -1e30f, mr = -1e30f;
#pragma unroll
        for (int j = 0; j < 8; j++) {
            int k = j * 256 + tid;
            c[j] = pc[k] * 25.0f * cs[j];
            r[j] = pr[k] * 25.0f;
            mc = fmaxf(mc, c[j]);
            mr = fmaxf(mr, r[j]);
        }
        mc = blockReduceMax(mc);
        mr = blockReduceMax(mr);
        float sc = 0.f, sr = 0.f;
#pragma unroll
        for (int j = 0; j < 8; j++) {
            c[j] = expf(c[j] - mc);
            r[j] = expf(r[j] - mr);
            sc += c[j];
            sr += r[j];
        }
        sc = blockReduceSum(sc);
        sr = blockReduceSum(sr);
        float ic = 0.5f / sc, ir = 0.5f / sr;
        size_t pb = ((size_t)h * 512 + q) * 2048;
#pragma unroll
        for (int j = 0; j < 8; j++) {
            float a = c[j] * ic + r[j] * ir;
            __half hh, ll;
            split1(a, hh, ll);
            attn_h[pb + j * 256 + tid] = hh;
            attn_l[pb + j * 256 + tid] = ll;
            accum[j] += a;
        }
    }
#pragma unroll
    for (int j = 0; j < 8; j++) asum[(size_t)q * 2048 + j * 256 + tid] = accum[j];
}

// ------------- masked renormalized second-round weights (split) --------------
__global__ void __launch_bounds__(256)
mask_renorm(const float* __restrict__ asum, const float* __restrict__ simc,
            const float* __restrict__ simr,
            __half* __restrict__ s2h, __half* __restrict__ s2l,
            __half* __restrict__ owh, __half* __restrict__ owl)
{
    const int q = blockIdx.x;
    const int tid = threadIdx.x;
    float a[8];
    float mx = -1e30f;
#pragma unroll
    for (int j = 0; j < 8; j++) {
        a[j] = asum[(size_t)q * 2048 + j * 256 + tid] * 0.125f;
        mx = fmaxf(mx, a[j]);
    }
    mx = blockReduceMax(mx);
    float sum = 0.f;
#pragma unroll
    for (int j = 0; j < 8; j++) {
        a[j] = expf(a[j] - mx);
        sum += a[j];
    }
    sum = blockReduceSum(sum);
    float inv = 1.0f / sum;
    float sm = 0.f;
#pragma unroll
    for (int j = 0; j < 8; j++) {
        int k = j * 256 + tid;
        float m = (simc[(size_t)q * 2048 + k] * 0.125f > 0.75f) ? 1.0f : 0.0f;
        a[j] = a[j] * inv * m;
        sm += a[j];
    }
    sm = blockReduceSum(sm);
    inv = 1.0f / sm;
    float so = 0.f;
    float o[8];
#pragma unroll
    for (int j = 0; j < 8; j++) {
        int k = j * 256 + tid;
        a[j] *= inv;
        __half hh, ll;
        split1(a[j], hh, ll);
        s2h[(size_t)q * 2048 + k] = hh;
        s2l[(size_t)q * 2048 + k] = ll;
        float m = (simr[(size_t)q * 2048 + k] * 0.125f > 0.99f) ? 1.0f : 0.0f;
        o[j] = a[j] * m;
        so += o[j];
    }
    so = blockReduceSum(so);
    inv = 1.0f / so;
#pragma unroll
    for (int j = 0; j < 8; j++) {
        float v = o[j] * inv;
        __half hh, ll;
        split1(v, hh, ll);
        owh[(size_t)q * 2048 + j * 256 + tid] = hh;
        owl[(size_t)q * 2048 + j * 256 + tid] = ll;
    }
}

// -------------------- copy x_ori into concat (split) -------------------------
__global__ void __launch_bounds__(256)
copy_xori(const float* __restrict__ kv, __half* __restrict__ xh,
          __half* __restrict__ xl)
{
    int z = blockIdx.y;
    kv += (size_t)z * 4 * Mi;
    xh += (size_t)z * 2 * Mi;
    xl += (size_t)z * 2 * Mi;
    int idx = blockIdx.x * 256 + threadIdx.x;
    int q = idx >> 8;
    int c4 = idx & 255;
    size_t off = (size_t)q * 2048 + 1024 + (size_t)c4 * 4;
    float4 v = *(const float4*)(kv + off);
    uint2 h, l;
    split4(v, h, l);
    *(uint2*)(xh + off) = h;
    *(uint2*)(xl + off) = l;
}

// ------------------------------ bias copy ------------------------------------
__global__ void copy_bias(const float* __restrict__ b0, const float* __restrict__ b1,
                          float* __restrict__ dst)
{
    int i = blockIdx.x * 256 + threadIdx.x;
    if (i < 2048) { dst[i] = b0[i]; dst[2048 + i] = b1[i]; }
}

// --------------------------------- launch ------------------------------------
extern "C" void kernel_launch(void* const* d_in, const int* in_sizes, int n_in,
                              void* d_out, int out_size)
{
    const float* x_cls     = (const float*)d_in[0];
    const float* x_reg     = (const float*)d_in[1];
    const float* cls_score = (const float*)d_in[2];
    const float* W_q_cls   = (const float*)d_in[4];
    const float* W_kv_cls  = (const float*)d_in[5];
    const float* W_q_reg   = (const float*)d_in[6];
    const float* W_kv_reg  = (const float*)d_in[7];
    const float* W_lin     = (const float*)d_in[8];
    const float* b_lin     = (const float*)d_in[9];
    const float* W_lin_reg = (const float*)d_in[10];
    const float* b_lin_reg = (const float*)d_in[11];
    float* out = (float*)d_out;

    float* F = nullptr;
    __half* Hp = nullptr;
    cudaGetSymbolAddress((void**)&F, g_scratch);
    cudaGetSymbolAddress((void**)&Hp, g_half);

    float* qc   = F + F_QC;
    float* kvc  = F + F_KVC;
    float* scc  = F + F_SCC;
    float* scr  = F + F_SCR;
    float* asum = F + F_ASUM;
    float* simc = F + F_SIMC;
    float* simr = F + F_SIMR;
    float* bias2 = F + F_BIAS;

    // smem: stage = 2*A + 2*B planes (80B rows)
    constexpr int SM_BIG = 2 * (2 * 128 * 80 + 2 * 128 * 80);  // 81920
    constexpr int SM_SML = 2 * (2 * 64 * 80 + 2 * 128 * 80);   // 61440

    // instantiations: big = 128x128 (warp 64x64); small = 64x128 (warp 32x64)
    auto big_f    = hgemm<128, 128, 64, 64, false, true, false>;
    auto big_bias = hgemm<128, 128, 64, 64, true, true, false>;
    auto sml_f    = hgemm<64, 128, 32, 64, false, true, false>;
    auto sml_s    = hgemm<64, 128, 32, 64, false, false, true>;
    cudaFuncSetAttribute(big_f, cudaFuncAttributeMaxDynamicSharedMemorySize, SM_BIG);
    cudaFuncSetAttribute(big_bias, cudaFuncAttributeMaxDynamicSharedMemorySize, SM_BIG);
    cudaFuncSetAttribute(sml_f, cudaFuncAttributeMaxDynamicSharedMemorySize, SM_SML);
    cudaFuncSetAttribute(sml_s, cudaFuncAttributeMaxDynamicSharedMemorySize, SM_SML);

    dim3 tb(32, 8);
    const long long OSTR = 512LL * 3072;   // out branch stride

    // 0) transpose+split weights; split x; copy biases
    transpose_split<<<dim3(32, 32), tb>>>(W_q_cls, Hp + HWQCH, Hp + HWQCL, 1024, 1024);
    transpose_split<<<dim3(32, 32), tb>>>(W_q_reg, Hp + HWQRH, Hp + HWQRL, 1024, 1024);
    transpose_split<<<dim3(64, 32), tb>>>(W_kv_cls, Hp + HWKCH, Hp + HWKCL, 2048, 1024);
    transpose_split<<<dim3(64, 32), tb>>>(W_kv_reg, Hp + HWKRH, Hp + HWKRL, 2048, 1024);
    transpose_split<<<dim3(64, 64), tb>>>(W_lin, Hp + HWLCH, Hp + HWLCL, 2048, 2048);
    transpose_split<<<dim3(64, 64), tb>>>(W_lin_reg, Hp + HWLRH, Hp + HWLRL, 2048, 2048);
    split_f16<<<2048, 256>>>(x_cls, Hp + HXCH, Hp + HXCL, 2048 * 256);
    split_f16<<<2048, 256>>>(x_reg, Hp + HXRH, Hp + HXRL, 2048 * 256);
    copy_bias<<<8, 256>>>(b_lin, b_lin_reg, bias2);

    // 1) q projections (small tiles): M=512,N=1024,K=1024, z=branch
    sml_f<<<dim3(8, 8, 2), 128, SM_SML>>>(
        Hp + HXCH, Hp + HXCL, Hp + HWQCH, Hp + HWQCL, nullptr,
        qc, nullptr, nullptr, 1024, 1024, 1024, 1024,
        2, 4 * Mi, 0, 2 * Mi, 0, Mi / 2, 0, 0);
    // kv projections (big): M=2048,N=2048,K=1024
    big_f<<<dim3(16, 16, 2), 128, SM_BIG>>>(
        Hp + HXCH, Hp + HXCL, Hp + HWKCH, Hp + HWKCL, nullptr,
        kvc, nullptr, nullptr, 1024, 1024, 1024, 2048,
        2, 4 * Mi, 0, 4 * Mi, 0, 4 * Mi, 0, 0);

    // 2) L2 norms + split (branch batched); transpose+split raw v
    l2norm_split<<<dim3(512, 2), 256>>>(qc, Hp + HQCH, Hp + HQCL,
                                        1024, 1024, 512 * 8, Mi / 2, Mi);
    l2norm_split<<<dim3(2048, 2), 256>>>(kvc, Hp + HKCH, Hp + HKCL,
                                         2048, 1024, 2048 * 8, 4 * Mi, 4 * Mi);
    l2norm_split<<<dim3(2048, 2), 256>>>(kvc + 1024, Hp + HVNCH, Hp + HVNCL,
                                         2048, 1024, 2048 * 8, 4 * Mi, 4 * Mi);
    transpose_split<<<dim3(32, 64), tb>>>(kvc + 1024, Hp + HVTCH, Hp + HVTCL, 2048, 2048);
    transpose_split<<<dim3(32, 64), tb>>>(kvc + 4 * Mi + 1024, Hp + HVTRH, Hp + HVTRL,
                                          2048, 2048);

    // 3) scores (big): z = branch*8 + head (z1=head, z2=branch). M=512,N=2048,K=128
    big_f<<<dim3(16, 4, 16), 128, SM_BIG>>>(
        Hp + HQCH, Hp + HQCL, Hp + HKCH, Hp + HKCL, nullptr,
        scc, nullptr, nullptr, 128, 1024, 1024, 2048,
        8, 128, Mi, 128, 4 * Mi, Mi, 8 * Mi, 0);

    // 4) v-sims (big): M=512,N=2048,K=1024, z=branch
    big_f<<<dim3(16, 4, 2), 128, SM_BIG>>>(
        Hp + HVNCH, Hp + HVNCL, Hp + HVNCH, Hp + HVNCL, nullptr,
        simc, nullptr, nullptr, 1024, 1024, 1024, 2048,
        2, 4 * Mi, 0, 4 * Mi, 0, Mi, 0, 0);

    // 5) softmax blend -> split attn + asum
    softmax_combine<<<512, 256>>>(scc, scr, cls_score, Hp + HATH, Hp + HATL, asum);

    // 6) attn@v (small, split out): M=512,N=128 per head, K=2048. z1=head
    sml_s<<<dim3(1, 8, 16), 128, SM_SML>>>(
        Hp + HATH, Hp + HATL, Hp + HVTCH, Hp + HVTCL, nullptr,
        nullptr, Hp + HXCCH, Hp + HXCCL, 2048, 2048, 2048, 2048,
        8, Mi, 0, 128LL * 2048, 4 * Mi, 128, 2 * Mi, 0);

    // 7) x_ori into concat cols [1024,2048), both branches
    copy_xori<<<dim3(512, 2), 256>>>(kvc, Hp + HXCCH, Hp + HXCCL);

    // 8) second-round masked weights
    mask_renorm<<<512, 256>>>(asum, simc, simr,
                              Hp + HS2H, Hp + HS2L, Hp + HOWH, Hp + HOWL);

    // 9) output linears (big + bias): M=512,N=2048,K=2048, z=branch
    big_bias<<<dim3(16, 4, 2), 128, SM_BIG>>>(
        Hp + HXCCH, Hp + HXCCL, Hp + HWLCH, Hp + HWLCL, bias2,
        out + 1024, nullptr, nullptr, 2048, 2048, 2048, 3072,
        2, 2 * Mi, 0, 8 * Mi, 0, OSTR, 0, 2048);

    // 10) support features (small): M=512,N=1024,K=2048, z=branch
    sml_f<<<dim3(8, 8, 2), 128, SM_SML>>>(
        Hp + HS2H, Hp + HS2L, Hp + HVTCH, Hp + HVTCL, nullptr,
        out, nullptr, nullptr, 2048, 2048, 2048, 3072,
        2, 2 * Mi, 0, 4 * Mi, 0, OSTR, 0, 0);
}